// round 2
// baseline (speedup 1.0000x reference)
#include <cuda_runtime.h>
#include <cuda_bf16.h>
#include <math.h>

#define N_NODES 50000
#define N_EDGES 800000
#define N_GRAPHS 256
#define D_HID 256

// ---------------- scratch (device globals; no allocation in kernel_launch) ---
__device__ float g_dinv[N_NODES];
__device__ int   g_deg[N_NODES];
__device__ int   g_rowptr[N_NODES + 1];
__device__ int   g_cursor[N_NODES];
__device__ int   g_colidx[N_EDGES];
__device__ float g_aggx[(size_t)N_NODES * 16];
__device__ float g_h1[(size_t)N_NODES * D_HID];
__device__ float g_agg[(size_t)N_NODES * D_HID];
__device__ float g_h2[(size_t)N_NODES * D_HID];
__device__ float g_pool[N_GRAPHS * D_HID];
__device__ int   g_cnt[N_GRAPHS];
__device__ int   g_is32_ei;     // 1 if edge_index is int32, 0 if int64
__device__ int   g_is32_batch;  // 1 if batch is int32, 0 if int64

__device__ __forceinline__ float selu_f(float v) {
    const float a = 1.6732632423543772f, s = 1.0507009873554805f;
    return v > 0.f ? s * v : s * a * (expf(v) - 1.f);
}

// Load index i from an array that is either int32 or int64 (values < 2^31).
__device__ __forceinline__ int load_idx(const void* p, long long i, int is32) {
    if (is32) return ((const int*)p)[i];
    return (int)((const long long*)p)[i];
}

// ---------------- dtype sniffing -------------------------------------------
// If data is int64 (little-endian, values >= 0 < 2^31), every odd int32 word is 0.
// If data is int32, odd words hold real (mostly nonzero) ids.
__global__ void detect_kernel(const int* __restrict__ ei32, const int* __restrict__ b32) {
    int i = blockIdx.x * blockDim.x + threadIdx.x;  // 4096 threads
    int v = ei32[2 * i + 1];   // within first 8192 words <= 1.6M int32 words (safe for both dtypes)
    if (v != 0) g_is32_ei = 1;       // benign racy set
    int bv = b32[2 * i + 1];   // batch has >= 50000 int32 words in either dtype; 8192 words safe
    if (bv != 0) g_is32_batch = 1;
}

// ---------------- CSR build ------------------------------------------------
__global__ void zero_kernel() {
    int i = blockIdx.x * blockDim.x + threadIdx.x;
    if (i < N_NODES) g_deg[i] = 0;
    if (i < N_GRAPHS * D_HID) g_pool[i] = 0.f;
    if (i < N_GRAPHS) g_cnt[i] = 0;
    if (i == 0) { g_is32_ei = 0; g_is32_batch = 0; }
}

__global__ void deg_kernel(const void* __restrict__ ei) {
    int e = blockIdx.x * blockDim.x + threadIdx.x;
    int is32 = g_is32_ei;
    if (e < N_EDGES) atomicAdd(&g_deg[load_idx(ei, (long long)N_EDGES + e, is32)], 1);
}

__global__ void dinv_kernel() {
    int i = blockIdx.x * blockDim.x + threadIdx.x;
    if (i < N_NODES) g_dinv[i] = rsqrtf((float)(g_deg[i] + 1));
}

// single-block exclusive scan of g_deg into g_rowptr
__global__ void scan_kernel() {
    __shared__ int sh[1024];
    __shared__ int carry;
    int tid = threadIdx.x;
    if (tid == 0) carry = 0;
    __syncthreads();
    for (int base = 0; base < N_NODES; base += 1024) {
        int i = base + tid;
        int v = (i < N_NODES) ? g_deg[i] : 0;
        sh[tid] = v;
        __syncthreads();
        for (int off = 1; off < 1024; off <<= 1) {
            int t = (tid >= off) ? sh[tid - off] : 0;
            __syncthreads();
            sh[tid] += t;
            __syncthreads();
        }
        int c = carry;
        if (i < N_NODES) g_rowptr[i] = c + sh[tid] - v;
        __syncthreads();
        if (tid == 0) carry = c + sh[1023];
        __syncthreads();
    }
    if (tid == 0) g_rowptr[N_NODES] = carry;
}

__global__ void cursor_kernel() {
    int i = blockIdx.x * blockDim.x + threadIdx.x;
    if (i < N_NODES) g_cursor[i] = g_rowptr[i];
}

__global__ void fill_kernel(const void* __restrict__ ei) {
    int e = blockIdx.x * blockDim.x + threadIdx.x;
    int is32 = g_is32_ei;
    if (e < N_EDGES) {
        int d = load_idx(ei, (long long)N_EDGES + e, is32);
        int p = atomicAdd(&g_cursor[d], 1);
        g_colidx[p] = load_idx(ei, e, is32);
    }
}

// ---------------- layer 1: aggregate x (14-dim), then GEMM ------------------
__global__ void agg1_kernel(const float* __restrict__ x) {
    int w = (blockIdx.x * blockDim.x + threadIdx.x) >> 5;
    int lane = threadIdx.x & 31;
    if (w >= N_NODES) return;
    float di = g_dinv[w];
    float acc = 0.f;
    if (lane < 14) acc = di * x[(size_t)w * 14 + lane];
    int e0 = g_rowptr[w], e1 = g_rowptr[w + 1];
    for (int e = e0; e < e1; e++) {
        int s = g_colidx[e];
        float ds = g_dinv[s];
        if (lane < 14) acc += ds * x[(size_t)s * 14 + lane];
    }
    if (lane < 16) g_aggx[(size_t)w * 16 + lane] = (lane < 14) ? di * acc : 0.f;
}

__global__ void gemm1_kernel(const float* __restrict__ W1, const float* __restrict__ b1) {
    __shared__ __align__(16) float sx[32][16];
    int row0 = blockIdx.x * 32;
    int tid = threadIdx.x;  // 256
    #pragma unroll
    for (int it = 0; it < 2; it++) {
        int idx = tid + it * 256;
        int r = idx >> 4, c = idx & 15;
        int row = row0 + r;
        sx[r][c] = (row < N_NODES) ? g_aggx[(size_t)row * 16 + c] : 0.f;
    }
    __syncthreads();
    float w[14];
    #pragma unroll
    for (int k = 0; k < 14; k++) w[k] = W1[k * 256 + tid];
    float bj = b1[tid];
    for (int r = 0; r < 32; r++) {
        int row = row0 + r;
        if (row >= N_NODES) break;
        float acc = bj;
        #pragma unroll
        for (int k = 0; k < 14; k++) acc += sx[r][k] * w[k];
        g_h1[(size_t)row * 256 + tid] = selu_f(acc);
    }
}

// ---------------- layer 2: aggregate h1 (256-dim), warp per node ------------
__global__ void agg2_kernel() {
    int w = (blockIdx.x * blockDim.x + threadIdx.x) >> 5;
    int lane = threadIdx.x & 31;
    if (w >= N_NODES) return;
    float di = g_dinv[w];
    const float4* self = (const float4*)(g_h1 + (size_t)w * 256);
    float4 a0 = self[2 * lane], a1 = self[2 * lane + 1];
    float4 s0 = make_float4(di * a0.x, di * a0.y, di * a0.z, di * a0.w);
    float4 s1 = make_float4(di * a1.x, di * a1.y, di * a1.z, di * a1.w);
    int e0 = g_rowptr[w], e1 = g_rowptr[w + 1];
    for (int e = e0; e < e1; e++) {
        int s = g_colidx[e];
        float ds = g_dinv[s];
        const float4* sp = (const float4*)(g_h1 + (size_t)s * 256);
        float4 v0 = sp[2 * lane], v1 = sp[2 * lane + 1];
        s0.x += ds * v0.x; s0.y += ds * v0.y; s0.z += ds * v0.z; s0.w += ds * v0.w;
        s1.x += ds * v1.x; s1.y += ds * v1.y; s1.z += ds * v1.z; s1.w += ds * v1.w;
    }
    float4* op = (float4*)(g_agg + (size_t)w * 256);
    op[2 * lane]     = make_float4(di * s0.x, di * s0.y, di * s0.z, di * s0.w);
    op[2 * lane + 1] = make_float4(di * s1.x, di * s1.y, di * s1.z, di * s1.w);
}

// ---------------- GEMM2: [50000,256] @ [256,256] + bias + selu --------------
#define BM 64
#define BN 64
#define BK 16
__global__ void gemm2_kernel(const float* __restrict__ B, const float* __restrict__ bias) {
    __shared__ __align__(16) float As[BK][BM];
    __shared__ __align__(16) float Bs[BK][BN];
    int m0 = blockIdx.x * BM, n0 = blockIdx.y * BN;
    int tid = threadIdx.x;  // 256
    int tx = tid & 15, ty = tid >> 4;
    int ar = tid >> 2;            // 0..63
    int ac = (tid & 3) * 4;       // 0,4,8,12
    int br = tid >> 4;            // 0..15
    int bc = (tid & 15) * 4;      // 0..60
    float acc[4][4];
    #pragma unroll
    for (int i = 0; i < 4; i++)
        #pragma unroll
        for (int j = 0; j < 4; j++) acc[i][j] = 0.f;

    for (int k0 = 0; k0 < 256; k0 += BK) {
        float4 av = make_float4(0.f, 0.f, 0.f, 0.f);
        if (m0 + ar < N_NODES)
            av = *(const float4*)(g_agg + (size_t)(m0 + ar) * 256 + k0 + ac);
        As[ac + 0][ar] = av.x; As[ac + 1][ar] = av.y;
        As[ac + 2][ar] = av.z; As[ac + 3][ar] = av.w;
        float4 bv = *(const float4*)(B + (size_t)(k0 + br) * 256 + n0 + bc);
        *(float4*)&Bs[br][bc] = bv;
        __syncthreads();
        #pragma unroll
        for (int k = 0; k < BK; k++) {
            float4 a = *(float4*)&As[k][ty * 4];
            float4 b = *(float4*)&Bs[k][tx * 4];
            acc[0][0] += a.x * b.x; acc[0][1] += a.x * b.y; acc[0][2] += a.x * b.z; acc[0][3] += a.x * b.w;
            acc[1][0] += a.y * b.x; acc[1][1] += a.y * b.y; acc[1][2] += a.y * b.z; acc[1][3] += a.y * b.w;
            acc[2][0] += a.z * b.x; acc[2][1] += a.z * b.y; acc[2][2] += a.z * b.z; acc[2][3] += a.z * b.w;
            acc[3][0] += a.w * b.x; acc[3][1] += a.w * b.y; acc[3][2] += a.w * b.z; acc[3][3] += a.w * b.w;
        }
        __syncthreads();
    }
    #pragma unroll
    for (int i = 0; i < 4; i++) {
        int m = m0 + ty * 4 + i;
        if (m < N_NODES) {
            #pragma unroll
            for (int j = 0; j < 4; j++) {
                int n = n0 + tx * 4 + j;
                g_h2[(size_t)m * 256 + n] = selu_f(acc[i][j] + bias[n]);
            }
        }
    }
}

// ---------------- pooling (batch sorted -> run-length local reduce) ---------
__global__ void count_kernel(const void* __restrict__ batch) {
    int i = blockIdx.x * blockDim.x + threadIdx.x;
    int is32 = g_is32_batch;
    if (i < N_NODES) atomicAdd(&g_cnt[load_idx(batch, i, is32)], 1);
}

__global__ void pool_kernel(const void* __restrict__ batch) {
    int c = threadIdx.x;  // 0..255
    int is32 = g_is32_batch;
    int n0 = blockIdx.x * 64;
    int n1 = n0 + 64;
    if (n1 > N_NODES) n1 = N_NODES;
    int cur = load_idx(batch, n0, is32);
    float acc = 0.f;
    for (int n = n0; n < n1; n++) {
        int g = load_idx(batch, n, is32);
        if (g != cur) {
            atomicAdd(&g_pool[cur * 256 + c], acc);
            acc = 0.f;
            cur = g;
        }
        acc += g_h2[(size_t)n * 256 + c];
    }
    atomicAdd(&g_pool[cur * 256 + c], acc);
}

// ---------------- head: selu -> fc1+selu -> fc2 -> log_softmax --------------
__global__ void head_kernel(const float* __restrict__ fc1w, const float* __restrict__ fc1b,
                            const float* __restrict__ fc2w, const float* __restrict__ fc2b,
                            float* __restrict__ out) {
    __shared__ __align__(16) float sp[256];
    __shared__ __align__(16) float sg[128];
    __shared__ float slog[2];
    int g = blockIdx.x, t = threadIdx.x;  // 128 threads
    float c = fmaxf((float)g_cnt[g], 1.0f);
    for (int j = t; j < 256; j += 128) sp[j] = selu_f(g_pool[g * 256 + j] / c);
    __syncthreads();
    float acc = fc1b[t];
    for (int k = 0; k < 256; k++) acc += sp[k] * fc1w[k * 128 + t];
    sg[t] = selu_f(acc);
    __syncthreads();
    if (t < 2) {
        float a = fc2b[t];
        for (int k = 0; k < 128; k++) a += sg[k] * fc2w[k * 2 + t];
        slog[t] = a;
    }
    __syncthreads();
    if (t < 2) {
        float m = fmaxf(slog[0], slog[1]);
        float lse = m + logf(expf(slog[0] - m) + expf(slog[1] - m));
        out[g * 2 + t] = slog[t] - lse;
    }
}

// ---------------- launch ----------------------------------------------------
extern "C" void kernel_launch(void* const* d_in, const int* in_sizes, int n_in,
                              void* d_out, int out_size) {
    const float* x     = (const float*)d_in[0];
    const void*  ei    = d_in[1];
    const void*  batch = d_in[2];
    const float* W1  = (const float*)d_in[3];
    const float* b1  = (const float*)d_in[4];
    const float* W2  = (const float*)d_in[5];
    const float* b2  = (const float*)d_in[6];
    const float* f1w = (const float*)d_in[7];
    const float* f1b = (const float*)d_in[8];
    const float* f2w = (const float*)d_in[9];
    const float* f2b = (const float*)d_in[10];
    float* out = (float*)d_out;

    zero_kernel<<<256, 256>>>();
    detect_kernel<<<16, 256>>>((const int*)ei, (const int*)batch);
    deg_kernel<<<(N_EDGES + 255) / 256, 256>>>(ei);
    dinv_kernel<<<(N_NODES + 255) / 256, 256>>>();
    scan_kernel<<<1, 1024>>>();
    cursor_kernel<<<(N_NODES + 255) / 256, 256>>>();
    fill_kernel<<<(N_EDGES + 255) / 256, 256>>>(ei);

    agg1_kernel<<<(N_NODES * 32 + 255) / 256, 256>>>(x);
    gemm1_kernel<<<(N_NODES + 31) / 32, 256>>>(W1, b1);

    agg2_kernel<<<(N_NODES * 32 + 255) / 256, 256>>>();
    {
        dim3 grid((N_NODES + BM - 1) / BM, 256 / BN);
        gemm2_kernel<<<grid, 256>>>(W2, b2);
    }

    count_kernel<<<(N_NODES + 255) / 256, 256>>>(batch);
    pool_kernel<<<(N_NODES + 63) / 64, 256>>>(batch);
    head_kernel<<<N_GRAPHS, 128>>>(f1w, f1b, f2w, f2b, out);
}

// round 4
// speedup vs baseline: 1.2249x; 1.2249x over previous
#include <cuda_runtime.h>
#include <cuda_bf16.h>
#include <math.h>

#define N_NODES 50000
#define N_EDGES 800000
#define N_GRAPHS 256
#define D_HID 256
#define SCAN_B 1024
#define N_SCANBLK ((N_NODES + SCAN_B - 1) / SCAN_B)   // 49

// ---------------- scratch (device globals) ----------------------------------
__device__ float g_dinv[N_NODES];
__device__ int   g_deg[N_NODES];
__device__ int   g_rowptr[N_NODES + 1];
__device__ int   g_cursor[N_NODES];
__device__ int   g_colidx[N_EDGES];
__device__ int   g_scantmp[N_NODES];
__device__ int   g_blockoff[N_SCANBLK + 1];
__device__ int   g_blocksum[N_SCANBLK];
__device__ float g_aggx[(size_t)N_NODES * 16];
__device__ float g_h1[(size_t)N_NODES * D_HID];
__device__ float g_agg[(size_t)N_NODES * D_HID];
__device__ float g_h2[(size_t)N_NODES * D_HID];
__device__ float g_pool[N_GRAPHS * D_HID];
__device__ int   g_cnt[N_GRAPHS];
__device__ int   g_is32_ei;
__device__ int   g_is32_batch;

__device__ __forceinline__ float selu_f(float v) {
    const float a = 1.6732632423543772f, s = 1.0507009873554805f;
    return v > 0.f ? s * v : s * a * (expf(v) - 1.f);
}

__device__ __forceinline__ int load_idx(const void* p, long long i, int is32) {
    if (is32) return ((const int*)p)[i];
    return (int)((const long long*)p)[i];
}

// ---------------- dtype sniff (self-contained, writes flags) ----------------
__global__ void detect_kernel(const int* __restrict__ ei32, const int* __restrict__ b32) {
    __shared__ int s_ei, s_b;
    int t = threadIdx.x;  // 1024
    if (t == 0) { s_ei = 0; s_b = 0; }
    __syncthreads();
    int v = 0, w = 0;
    #pragma unroll
    for (int j = 0; j < 4; j++) {
        int i = t + j * 1024;           // odd words within first 8192 (safe either dtype)
        v |= ei32[2 * i + 1];
        w |= b32[2 * i + 1];
    }
    if (v) s_ei = 1;
    if (w) s_b = 1;
    __syncthreads();
    if (t == 0) { g_is32_ei = s_ei; g_is32_batch = s_b; }
}

// ---------------- init ------------------------------------------------------
__global__ void zero_kernel() {
    int i = blockIdx.x * blockDim.x + threadIdx.x;
    if (i < N_NODES) g_deg[i] = 0;
    if (i < N_GRAPHS * D_HID) g_pool[i] = 0.f;
    if (i < N_GRAPHS) g_cnt[i] = 0;
}

// degree histogram + graph-count histogram in one pass
__global__ void deg_count_kernel(const void* __restrict__ ei, const void* __restrict__ batch) {
    int i = blockIdx.x * blockDim.x + threadIdx.x;
    if (i < N_EDGES) atomicAdd(&g_deg[load_idx(ei, (long long)N_EDGES + i, g_is32_ei)], 1);
    if (i < N_NODES) atomicAdd(&g_cnt[load_idx(batch, i, g_is32_batch)], 1);
}

// ---------------- 3-phase exclusive scan of g_deg ---------------------------
__global__ void scan_local() {   // grid N_SCANBLK, block 1024
    __shared__ int warp_sums[32];
    int b = blockIdx.x, t = threadIdx.x;
    int i = b * SCAN_B + t;
    int v = (i < N_NODES) ? g_deg[i] : 0;
    int x = v;
    #pragma unroll
    for (int off = 1; off < 32; off <<= 1) {
        int y = __shfl_up_sync(0xffffffffu, x, off);
        if ((t & 31) >= off) x += y;
    }
    if ((t & 31) == 31) warp_sums[t >> 5] = x;
    __syncthreads();
    if (t < 32) {
        int s = warp_sums[t];
        #pragma unroll
        for (int off = 1; off < 32; off <<= 1) {
            int y = __shfl_up_sync(0xffffffffu, s, off);
            if (t >= off) s += y;
        }
        warp_sums[t] = s;
    }
    __syncthreads();
    int inc = x + ((t >= 32) ? warp_sums[(t >> 5) - 1] : 0);
    if (i < N_NODES) g_scantmp[i] = inc;
    if (t == SCAN_B - 1) g_blocksum[b] = inc;
}

__global__ void scan_sums() {    // 1 block, 64 threads
    __shared__ int sh[64];
    int t = threadIdx.x;
    sh[t] = (t < N_SCANBLK) ? g_blocksum[t] : 0;
    __syncthreads();
    #pragma unroll
    for (int off = 1; off < 64; off <<= 1) {
        int y = (t >= off) ? sh[t - off] : 0;
        __syncthreads();
        sh[t] += y;
        __syncthreads();
    }
    if (t == 0) g_blockoff[0] = 0;
    g_blockoff[t + 1] = sh[t];
}

// finish scan + cursor init + dinv (all consume g_deg / scan results)
__global__ void scan_finish() {
    int i = blockIdx.x * blockDim.x + threadIdx.x;
    if (i < N_NODES) {
        int d = g_deg[i];
        int r = g_scantmp[i] - d + g_blockoff[i >> 10];
        g_rowptr[i] = r;
        g_cursor[i] = r;
        g_dinv[i] = rsqrtf((float)(d + 1));
    }
    if (i == 0) g_rowptr[N_NODES] = g_blockoff[N_SCANBLK];
}

__global__ void fill_kernel(const void* __restrict__ ei) {
    int e = blockIdx.x * blockDim.x + threadIdx.x;
    int is32 = g_is32_ei;
    if (e < N_EDGES) {
        int d = load_idx(ei, (long long)N_EDGES + e, is32);
        int p = atomicAdd(&g_cursor[d], 1);
        g_colidx[p] = load_idx(ei, e, is32);
    }
}

// ---------------- layer 1: aggregate x (14-dim), then GEMM ------------------
__global__ void agg1_kernel(const float* __restrict__ x) {
    int w = (blockIdx.x * blockDim.x + threadIdx.x) >> 5;
    int lane = threadIdx.x & 31;
    if (w >= N_NODES) return;
    float di = g_dinv[w];
    float acc = 0.f;
    if (lane < 14) acc = di * x[(size_t)w * 14 + lane];
    int e0 = g_rowptr[w], e1 = g_rowptr[w + 1];
    for (int e = e0; e < e1; e++) {
        int s = g_colidx[e];
        float ds = g_dinv[s];
        if (lane < 14) acc += ds * x[(size_t)s * 14 + lane];
    }
    if (lane < 16) g_aggx[(size_t)w * 16 + lane] = (lane < 14) ? di * acc : 0.f;
}

__global__ void gemm1_kernel(const float* __restrict__ W1, const float* __restrict__ b1) {
    __shared__ __align__(16) float sx[32][16];
    int row0 = blockIdx.x * 32;
    int tid = threadIdx.x;  // 256
    #pragma unroll
    for (int it = 0; it < 2; it++) {
        int idx = tid + it * 256;
        int r = idx >> 4, c = idx & 15;
        int row = row0 + r;
        sx[r][c] = (row < N_NODES) ? g_aggx[(size_t)row * 16 + c] : 0.f;
    }
    __syncthreads();
    float w[14];
    #pragma unroll
    for (int k = 0; k < 14; k++) w[k] = W1[k * 256 + tid];
    float bj = b1[tid];
    for (int r = 0; r < 32; r++) {
        int row = row0 + r;
        if (row >= N_NODES) break;
        float acc = bj;
        #pragma unroll
        for (int k = 0; k < 14; k++) acc += sx[r][k] * w[k];
        g_h1[(size_t)row * 256 + tid] = selu_f(acc);
    }
}

// ---------------- layer 2: aggregate h1 (256-dim), warp per node ------------
__global__ void agg2_kernel() {
    int w = (blockIdx.x * blockDim.x + threadIdx.x) >> 5;
    int lane = threadIdx.x & 31;
    if (w >= N_NODES) return;
    float di = g_dinv[w];
    const float4* self = (const float4*)(g_h1 + (size_t)w * 256);
    float4 a0 = self[2 * lane], a1 = self[2 * lane + 1];
    float4 s0 = make_float4(di * a0.x, di * a0.y, di * a0.z, di * a0.w);
    float4 s1 = make_float4(di * a1.x, di * a1.y, di * a1.z, di * a1.w);
    int e0 = g_rowptr[w], e1 = g_rowptr[w + 1];
    for (int e = e0; e < e1; e++) {
        int s = g_colidx[e];
        float ds = g_dinv[s];
        const float4* sp = (const float4*)(g_h1 + (size_t)s * 256);
        float4 v0 = sp[2 * lane], v1 = sp[2 * lane + 1];
        s0.x += ds * v0.x; s0.y += ds * v0.y; s0.z += ds * v0.z; s0.w += ds * v0.w;
        s1.x += ds * v1.x; s1.y += ds * v1.y; s1.z += ds * v1.z; s1.w += ds * v1.w;
    }
    float4* op = (float4*)(g_agg + (size_t)w * 256);
    op[2 * lane]     = make_float4(di * s0.x, di * s0.y, di * s0.z, di * s0.w);
    op[2 * lane + 1] = make_float4(di * s1.x, di * s1.y, di * s1.z, di * s1.w);
}

// ---------------- GEMM2: [50000,256]@[256,256], 128x128x8, 8x8 microtile ----
#define BM 128
#define BN 128
#define BK 8
__global__ void __launch_bounds__(256) gemm2_kernel(const float* __restrict__ B,
                                                    const float* __restrict__ bias) {
    __shared__ __align__(16) float As[BK][BM];
    __shared__ __align__(16) float Bs[BK][BN];
    int m0 = blockIdx.x * BM, n0 = blockIdx.y * BN;
    int tid = threadIdx.x;            // 256
    int a_row = tid >> 1;             // 0..127
    int a_col = (tid & 1) * 4;        // 0 or 4
    int b_row = tid >> 5;             // 0..7
    int b_col = (tid & 31) * 4;       // 0..124
    int tx = tid & 15, ty = tid >> 4; // 16x16 thread grid

    float acc[8][8];
    #pragma unroll
    for (int i = 0; i < 8; i++)
        #pragma unroll
        for (int j = 0; j < 8; j++) acc[i][j] = 0.f;

    for (int k0 = 0; k0 < 256; k0 += BK) {
        float4 av = make_float4(0.f, 0.f, 0.f, 0.f);
        if (m0 + a_row < N_NODES)
            av = *(const float4*)(g_agg + (size_t)(m0 + a_row) * 256 + k0 + a_col);
        As[a_col + 0][a_row] = av.x; As[a_col + 1][a_row] = av.y;
        As[a_col + 2][a_row] = av.z; As[a_col + 3][a_row] = av.w;
        float4 bv = *(const float4*)(B + (size_t)(k0 + b_row) * 256 + n0 + b_col);
        *(float4*)&Bs[b_row][b_col] = bv;
        __syncthreads();
        #pragma unroll
        for (int k = 0; k < BK; k++) {
            float4 a0 = *(float4*)&As[k][ty * 8];
            float4 a1 = *(float4*)&As[k][ty * 8 + 4];
            float4 b0 = *(float4*)&Bs[k][tx * 8];
            float4 b1 = *(float4*)&Bs[k][tx * 8 + 4];
            float am[8] = {a0.x, a0.y, a0.z, a0.w, a1.x, a1.y, a1.z, a1.w};
            float bn[8] = {b0.x, b0.y, b0.z, b0.w, b1.x, b1.y, b1.z, b1.w};
            #pragma unroll
            for (int i = 0; i < 8; i++)
                #pragma unroll
                for (int j = 0; j < 8; j++)
                    acc[i][j] += am[i] * bn[j];
        }
        __syncthreads();
    }
    #pragma unroll
    for (int i = 0; i < 8; i++) {
        int m = m0 + ty * 8 + i;
        if (m < N_NODES) {
            float4 o0, o1;
            int n = n0 + tx * 8;
            o0.x = selu_f(acc[i][0] + bias[n + 0]);
            o0.y = selu_f(acc[i][1] + bias[n + 1]);
            o0.z = selu_f(acc[i][2] + bias[n + 2]);
            o0.w = selu_f(acc[i][3] + bias[n + 3]);
            o1.x = selu_f(acc[i][4] + bias[n + 4]);
            o1.y = selu_f(acc[i][5] + bias[n + 5]);
            o1.z = selu_f(acc[i][6] + bias[n + 6]);
            o1.w = selu_f(acc[i][7] + bias[n + 7]);
            *(float4*)(g_h2 + (size_t)m * 256 + n)     = o0;
            *(float4*)(g_h2 + (size_t)m * 256 + n + 4) = o1;
        }
    }
}

// ---------------- pooling ----------------------------------------------------
__global__ void pool_kernel(const void* __restrict__ batch) {
    int c = threadIdx.x;  // 0..255
    int is32 = g_is32_batch;
    int n0 = blockIdx.x * 64;
    int n1 = n0 + 64;
    if (n1 > N_NODES) n1 = N_NODES;
    int cur = load_idx(batch, n0, is32);
    float acc = 0.f;
    for (int n = n0; n < n1; n++) {
        int g = load_idx(batch, n, is32);
        if (g != cur) {
            atomicAdd(&g_pool[cur * 256 + c], acc);
            acc = 0.f;
            cur = g;
        }
        acc += g_h2[(size_t)n * 256 + c];
    }
    atomicAdd(&g_pool[cur * 256 + c], acc);
}

// ---------------- head ------------------------------------------------------
__global__ void head_kernel(const float* __restrict__ fc1w, const float* __restrict__ fc1b,
                            const float* __restrict__ fc2w, const float* __restrict__ fc2b,
                            float* __restrict__ out) {
    __shared__ __align__(16) float sp[256];
    __shared__ __align__(16) float sg[128];
    __shared__ float slog[2];
    int g = blockIdx.x, t = threadIdx.x;  // 128 threads
    float c = fmaxf((float)g_cnt[g], 1.0f);
    for (int j = t; j < 256; j += 128) sp[j] = selu_f(g_pool[g * 256 + j] / c);
    __syncthreads();
    float acc = fc1b[t];
    for (int k = 0; k < 256; k++) acc += sp[k] * fc1w[k * 128 + t];
    sg[t] = selu_f(acc);
    __syncthreads();
    if (t < 2) {
        float a = fc2b[t];
        for (int k = 0; k < 128; k++) a += sg[k] * fc2w[k * 2 + t];
        slog[t] = a;
    }
    __syncthreads();
    if (t < 2) {
        float m = fmaxf(slog[0], slog[1]);
        float lse = m + logf(expf(slog[0] - m) + expf(slog[1] - m));
        out[g * 2 + t] = slog[t] - lse;
    }
}

// ---------------- launch ----------------------------------------------------
extern "C" void kernel_launch(void* const* d_in, const int* in_sizes, int n_in,
                              void* d_out, int out_size) {
    const float* x     = (const float*)d_in[0];
    const void*  ei    = d_in[1];
    const void*  batch = d_in[2];
    const float* W1  = (const float*)d_in[3];
    const float* b1  = (const float*)d_in[4];
    const float* W2  = (const float*)d_in[5];
    const float* b2  = (const float*)d_in[6];
    const float* f1w = (const float*)d_in[7];
    const float* f1b = (const float*)d_in[8];
    const float* f2w = (const float*)d_in[9];
    const float* f2b = (const float*)d_in[10];
    float* out = (float*)d_out;

    zero_kernel<<<256, 256>>>();
    detect_kernel<<<1, 1024>>>((const int*)ei, (const int*)batch);
    deg_count_kernel<<<(N_EDGES + 255) / 256, 256>>>(ei, batch);
    scan_local<<<N_SCANBLK, SCAN_B>>>();
    scan_sums<<<1, 64>>>();
    scan_finish<<<(N_NODES + 255) / 256, 256>>>();
    fill_kernel<<<(N_EDGES + 255) / 256, 256>>>(ei);

    agg1_kernel<<<(N_NODES * 32 + 255) / 256, 256>>>(x);
    gemm1_kernel<<<(N_NODES + 31) / 32, 256>>>(W1, b1);

    agg2_kernel<<<(N_NODES * 32 + 255) / 256, 256>>>();
    {
        dim3 grid((N_NODES + BM - 1) / BM, 256 / BN);
        gemm2_kernel<<<grid, 256>>>(W2, b2);
    }

    pool_kernel<<<(N_NODES + 63) / 64, 256>>>(batch);
    head_kernel<<<N_GRAPHS, 128>>>(f1w, f1b, f2w, f2b, out);
}

// round 5
// speedup vs baseline: 1.6193x; 1.3220x over previous
#include <cuda_runtime.h>
#include <cuda_bf16.h>
#include <math.h>

#define N_NODES 50000
#define N_EDGES 800000
#define N_GRAPHS 256
#define D_HID 256
#define SCAN_B 1024
#define N_SCANBLK ((N_NODES + SCAN_B - 1) / SCAN_B)   // 49

// ---------------- scratch (device globals) ----------------------------------
__device__ float g_dinv[N_NODES];
__device__ int   g_deg[N_NODES];
__device__ int   g_rowptr[N_NODES + 1];
__device__ int   g_cursor[N_NODES];
__device__ int   g_colidx[N_EDGES];
__device__ int   g_scantmp[N_NODES];
__device__ int   g_blockoff[N_SCANBLK + 1];
__device__ int   g_blocksum[N_SCANBLK];
__device__ float g_aggx[(size_t)N_NODES * 16];
__device__ float g_h1[(size_t)N_NODES * D_HID];
__device__ float g_agg[(size_t)N_NODES * D_HID];
__device__ float g_h2[(size_t)N_NODES * D_HID];
__device__ float g_pool[N_GRAPHS * D_HID];
__device__ int   g_cnt[N_GRAPHS];
__device__ int   g_is32_ei;
__device__ int   g_is32_batch;

__device__ __forceinline__ float selu_f(float v) {
    const float a = 1.6732632423543772f, s = 1.0507009873554805f;
    return v > 0.f ? s * v : s * a * (expf(v) - 1.f);
}

__device__ __forceinline__ int load_idx(const void* p, long long i, int is32) {
    if (is32) return ((const int*)p)[i];
    return (int)((const long long*)p)[i];
}

__device__ __forceinline__ unsigned f2tf32(float f) {
    unsigned r;
    asm("cvt.rna.tf32.f32 %0, %1;" : "=r"(r) : "f"(f));
    return r;
}

// ---------------- dtype sniff ------------------------------------------------
__global__ void detect_kernel(const int* __restrict__ ei32, const int* __restrict__ b32) {
    __shared__ int s_ei, s_b;
    int t = threadIdx.x;  // 1024
    if (t == 0) { s_ei = 0; s_b = 0; }
    __syncthreads();
    int v = 0, w = 0;
    #pragma unroll
    for (int j = 0; j < 4; j++) {
        int i = t + j * 1024;
        v |= ei32[2 * i + 1];
        w |= b32[2 * i + 1];
    }
    if (v) s_ei = 1;
    if (w) s_b = 1;
    __syncthreads();
    if (t == 0) { g_is32_ei = s_ei; g_is32_batch = s_b; }
}

// ---------------- init -------------------------------------------------------
__global__ void zero_kernel() {
    int i = blockIdx.x * blockDim.x + threadIdx.x;
    if (i < N_NODES) g_deg[i] = 0;
    if (i < N_GRAPHS * D_HID) g_pool[i] = 0.f;
    if (i < N_GRAPHS) g_cnt[i] = 0;
}

__global__ void deg_count_kernel(const void* __restrict__ ei, const void* __restrict__ batch) {
    int i = blockIdx.x * blockDim.x + threadIdx.x;
    if (i < N_EDGES) atomicAdd(&g_deg[load_idx(ei, (long long)N_EDGES + i, g_is32_ei)], 1);
    if (i < N_NODES) atomicAdd(&g_cnt[load_idx(batch, i, g_is32_batch)], 1);
}

// ---------------- 3-phase exclusive scan of g_deg ----------------------------
__global__ void scan_local() {
    __shared__ int warp_sums[32];
    int b = blockIdx.x, t = threadIdx.x;
    int i = b * SCAN_B + t;
    int v = (i < N_NODES) ? g_deg[i] : 0;
    int x = v;
    #pragma unroll
    for (int off = 1; off < 32; off <<= 1) {
        int y = __shfl_up_sync(0xffffffffu, x, off);
        if ((t & 31) >= off) x += y;
    }
    if ((t & 31) == 31) warp_sums[t >> 5] = x;
    __syncthreads();
    if (t < 32) {
        int s = warp_sums[t];
        #pragma unroll
        for (int off = 1; off < 32; off <<= 1) {
            int y = __shfl_up_sync(0xffffffffu, s, off);
            if (t >= off) s += y;
        }
        warp_sums[t] = s;
    }
    __syncthreads();
    int inc = x + ((t >= 32) ? warp_sums[(t >> 5) - 1] : 0);
    if (i < N_NODES) g_scantmp[i] = inc;
    if (t == SCAN_B - 1) g_blocksum[b] = inc;
}

__global__ void scan_sums() {
    __shared__ int sh[64];
    int t = threadIdx.x;
    sh[t] = (t < N_SCANBLK) ? g_blocksum[t] : 0;
    __syncthreads();
    #pragma unroll
    for (int off = 1; off < 64; off <<= 1) {
        int y = (t >= off) ? sh[t - off] : 0;
        __syncthreads();
        sh[t] += y;
        __syncthreads();
    }
    if (t == 0) g_blockoff[0] = 0;
    g_blockoff[t + 1] = sh[t];
}

__global__ void scan_finish() {
    int i = blockIdx.x * blockDim.x + threadIdx.x;
    if (i < N_NODES) {
        int d = g_deg[i];
        int r = g_scantmp[i] - d + g_blockoff[i >> 10];
        g_rowptr[i] = r;
        g_cursor[i] = r;
        g_dinv[i] = rsqrtf((float)(d + 1));
    }
    if (i == 0) g_rowptr[N_NODES] = g_blockoff[N_SCANBLK];
}

__global__ void fill_kernel(const void* __restrict__ ei) {
    int e = blockIdx.x * blockDim.x + threadIdx.x;
    int is32 = g_is32_ei;
    if (e < N_EDGES) {
        int d = load_idx(ei, (long long)N_EDGES + e, is32);
        int p = atomicAdd(&g_cursor[d], 1);
        g_colidx[p] = load_idx(ei, e, is32);
    }
}

// ---------------- layer 1 ----------------------------------------------------
__global__ void agg1_kernel(const float* __restrict__ x) {
    int w = (blockIdx.x * blockDim.x + threadIdx.x) >> 5;
    int lane = threadIdx.x & 31;
    if (w >= N_NODES) return;
    float di = g_dinv[w];
    float acc = 0.f;
    if (lane < 14) acc = di * x[(size_t)w * 14 + lane];
    int e0 = g_rowptr[w], e1 = g_rowptr[w + 1];
    for (int e = e0; e < e1; e++) {
        int s = g_colidx[e];
        float ds = g_dinv[s];
        if (lane < 14) acc += ds * x[(size_t)s * 14 + lane];
    }
    if (lane < 16) g_aggx[(size_t)w * 16 + lane] = (lane < 14) ? di * acc : 0.f;
}

__global__ void gemm1_kernel(const float* __restrict__ W1, const float* __restrict__ b1) {
    __shared__ __align__(16) float sx[32][16];
    int row0 = blockIdx.x * 32;
    int tid = threadIdx.x;  // 256
    #pragma unroll
    for (int it = 0; it < 2; it++) {
        int idx = tid + it * 256;
        int r = idx >> 4, c = idx & 15;
        int row = row0 + r;
        sx[r][c] = (row < N_NODES) ? g_aggx[(size_t)row * 16 + c] : 0.f;
    }
    __syncthreads();
    float w[14];
    #pragma unroll
    for (int k = 0; k < 14; k++) w[k] = W1[k * 256 + tid];
    float bj = b1[tid];
    for (int r = 0; r < 32; r++) {
        int row = row0 + r;
        if (row >= N_NODES) break;
        float acc = bj;
        #pragma unroll
        for (int k = 0; k < 14; k++) acc += sx[r][k] * w[k];
        g_h1[(size_t)row * 256 + tid] = selu_f(acc);
    }
}

// ---------------- layer 2 aggregate -----------------------------------------
__global__ void agg2_kernel() {
    int w = (blockIdx.x * blockDim.x + threadIdx.x) >> 5;
    int lane = threadIdx.x & 31;
    if (w >= N_NODES) return;
    float di = g_dinv[w];
    const float4* self = (const float4*)(g_h1 + (size_t)w * 256);
    float4 a0 = self[2 * lane], a1 = self[2 * lane + 1];
    float4 s0 = make_float4(di * a0.x, di * a0.y, di * a0.z, di * a0.w);
    float4 s1 = make_float4(di * a1.x, di * a1.y, di * a1.z, di * a1.w);
    int e0 = g_rowptr[w], e1 = g_rowptr[w + 1];
    for (int e = e0; e < e1; e++) {
        int s = g_colidx[e];
        float ds = g_dinv[s];
        const float4* sp = (const float4*)(g_h1 + (size_t)s * 256);
        float4 v0 = sp[2 * lane], v1 = sp[2 * lane + 1];
        s0.x += ds * v0.x; s0.y += ds * v0.y; s0.z += ds * v0.z; s0.w += ds * v0.w;
        s1.x += ds * v1.x; s1.y += ds * v1.y; s1.z += ds * v1.z; s1.w += ds * v1.w;
    }
    float4* op = (float4*)(g_agg + (size_t)w * 256);
    op[2 * lane]     = make_float4(di * s0.x, di * s0.y, di * s0.z, di * s0.w);
    op[2 * lane + 1] = make_float4(di * s1.x, di * s1.y, di * s1.z, di * s1.w);
}

// ---------------- GEMM2 via tf32 tensor cores --------------------------------
// C[50000,256] = g_agg[50000,256] @ W2[256,256]; block tile 128x128, K-chunk 32.
// 8 warps: 4 (m) x 2 (n); warp tile 32x64 = 2 x 8 m16n8k8 fragments.
#define GM 128
#define GN 128
#define GK 32
#define GS (GM + 4)   // smem row stride (132) -> conflict-free frag loads

__global__ void __launch_bounds__(256, 2) gemm2_tc(const float* __restrict__ W,
                                                   const float* __restrict__ bias) {
    __shared__ unsigned As[GK][GS];   // As[k][m], tf32 bits
    __shared__ unsigned Bs[GK][GS];   // Bs[k][n], tf32 bits
    int m0 = blockIdx.x * GM, n0 = blockIdx.y * GN;
    int tid = threadIdx.x;
    int lane = tid & 31, warp = tid >> 5;
    int wm = (warp >> 1) * 32;   // warp m-offset in tile
    int wn = (warp & 1) * 64;    // warp n-offset in tile
    int g = lane >> 2, tg = lane & 3;

    float d[2][8][4];
    #pragma unroll
    for (int mi = 0; mi < 2; mi++)
        #pragma unroll
        for (int ni = 0; ni < 8; ni++)
            #pragma unroll
            for (int q = 0; q < 4; q++) d[mi][ni][q] = 0.f;

    for (int k0 = 0; k0 < 256; k0 += GK) {
        // stage A (transposed into [k][m]) with tf32 convert
        #pragma unroll
        for (int it = 0; it < 4; it++) {
            int idx = tid + it * 256;        // 0..1023
            int row = idx >> 3;              // 0..127
            int c = (idx & 7) * 4;           // 0..28
            float4 av = make_float4(0.f, 0.f, 0.f, 0.f);
            if (m0 + row < N_NODES)
                av = *(const float4*)(g_agg + (size_t)(m0 + row) * 256 + k0 + c);
            As[c + 0][row] = f2tf32(av.x);
            As[c + 1][row] = f2tf32(av.y);
            As[c + 2][row] = f2tf32(av.z);
            As[c + 3][row] = f2tf32(av.w);
        }
        // stage B ([k][n]) with tf32 convert
        #pragma unroll
        for (int it = 0; it < 4; it++) {
            int idx = tid + it * 256;        // 0..1023
            int kr = idx >> 5;               // 0..31
            int nc = (idx & 31) * 4;         // 0..124
            float4 bv = *(const float4*)(W + (size_t)(k0 + kr) * 256 + n0 + nc);
            Bs[kr][nc + 0] = f2tf32(bv.x);
            Bs[kr][nc + 1] = f2tf32(bv.y);
            Bs[kr][nc + 2] = f2tf32(bv.z);
            Bs[kr][nc + 3] = f2tf32(bv.w);
        }
        __syncthreads();

        #pragma unroll
        for (int kk = 0; kk < GK; kk += 8) {
            unsigned a[2][4], b[8][2];
            #pragma unroll
            for (int mi = 0; mi < 2; mi++) {
                int mb = wm + mi * 16;
                a[mi][0] = As[kk + tg][mb + g];
                a[mi][1] = As[kk + tg][mb + g + 8];
                a[mi][2] = As[kk + tg + 4][mb + g];
                a[mi][3] = As[kk + tg + 4][mb + g + 8];
            }
            #pragma unroll
            for (int ni = 0; ni < 8; ni++) {
                int nb = wn + ni * 8;
                b[ni][0] = Bs[kk + tg][nb + g];
                b[ni][1] = Bs[kk + tg + 4][nb + g];
            }
            #pragma unroll
            for (int mi = 0; mi < 2; mi++)
                #pragma unroll
                for (int ni = 0; ni < 8; ni++)
                    asm volatile(
                        "mma.sync.aligned.m16n8k8.row.col.f32.tf32.tf32.f32 "
                        "{%0,%1,%2,%3},{%4,%5,%6,%7},{%8,%9},{%0,%1,%2,%3};"
                        : "+f"(d[mi][ni][0]), "+f"(d[mi][ni][1]),
                          "+f"(d[mi][ni][2]), "+f"(d[mi][ni][3])
                        : "r"(a[mi][0]), "r"(a[mi][1]), "r"(a[mi][2]), "r"(a[mi][3]),
                          "r"(b[ni][0]), "r"(b[ni][1]));
        }
        __syncthreads();
    }

    // epilogue: bias + selu + store
    #pragma unroll
    for (int mi = 0; mi < 2; mi++) {
        int r0 = m0 + wm + mi * 16 + g;
        #pragma unroll
        for (int ni = 0; ni < 8; ni++) {
            int col = n0 + wn + ni * 8 + 2 * tg;
            float bz0 = bias[col], bz1 = bias[col + 1];
            if (r0 < N_NODES) {
                float2 o = make_float2(selu_f(d[mi][ni][0] + bz0),
                                       selu_f(d[mi][ni][1] + bz1));
                *(float2*)(g_h2 + (size_t)r0 * 256 + col) = o;
            }
            int r1 = r0 + 8;
            if (r1 < N_NODES) {
                float2 o = make_float2(selu_f(d[mi][ni][2] + bz0),
                                       selu_f(d[mi][ni][3] + bz1));
                *(float2*)(g_h2 + (size_t)r1 * 256 + col) = o;
            }
        }
    }
}

// ---------------- pooling ----------------------------------------------------
__global__ void pool_kernel(const void* __restrict__ batch) {
    int c = threadIdx.x;  // 0..255
    int is32 = g_is32_batch;
    int n0 = blockIdx.x * 64;
    int n1 = n0 + 64;
    if (n1 > N_NODES) n1 = N_NODES;
    int cur = load_idx(batch, n0, is32);
    float acc = 0.f;
    for (int n = n0; n < n1; n++) {
        int g = load_idx(batch, n, is32);
        if (g != cur) {
            atomicAdd(&g_pool[cur * 256 + c], acc);
            acc = 0.f;
            cur = g;
        }
        acc += g_h2[(size_t)n * 256 + c];
    }
    atomicAdd(&g_pool[cur * 256 + c], acc);
}

// ---------------- head -------------------------------------------------------
__global__ void head_kernel(const float* __restrict__ fc1w, const float* __restrict__ fc1b,
                            const float* __restrict__ fc2w, const float* __restrict__ fc2b,
                            float* __restrict__ out) {
    __shared__ __align__(16) float sp[256];
    __shared__ __align__(16) float sg[128];
    __shared__ float slog[2];
    int g = blockIdx.x, t = threadIdx.x;  // 128 threads
    float c = fmaxf((float)g_cnt[g], 1.0f);
    for (int j = t; j < 256; j += 128) sp[j] = selu_f(g_pool[g * 256 + j] / c);
    __syncthreads();
    float acc = fc1b[t];
    for (int k = 0; k < 256; k++) acc += sp[k] * fc1w[k * 128 + t];
    sg[t] = selu_f(acc);
    __syncthreads();
    if (t < 2) {
        float a = fc2b[t];
        for (int k = 0; k < 128; k++) a += sg[k] * fc2w[k * 2 + t];
        slog[t] = a;
    }
    __syncthreads();
    if (t < 2) {
        float m = fmaxf(slog[0], slog[1]);
        float lse = m + logf(expf(slog[0] - m) + expf(slog[1] - m));
        out[g * 2 + t] = slog[t] - lse;
    }
}

// ---------------- launch -----------------------------------------------------
extern "C" void kernel_launch(void* const* d_in, const int* in_sizes, int n_in,
                              void* d_out, int out_size) {
    const float* x     = (const float*)d_in[0];
    const void*  ei    = d_in[1];
    const void*  batch = d_in[2];
    const float* W1  = (const float*)d_in[3];
    const float* b1  = (const float*)d_in[4];
    const float* W2  = (const float*)d_in[5];
    const float* b2  = (const float*)d_in[6];
    const float* f1w = (const float*)d_in[7];
    const float* f1b = (const float*)d_in[8];
    const float* f2w = (const float*)d_in[9];
    const float* f2b = (const float*)d_in[10];
    float* out = (float*)d_out;

    zero_kernel<<<256, 256>>>();
    detect_kernel<<<1, 1024>>>((const int*)ei, (const int*)batch);
    deg_count_kernel<<<(N_EDGES + 255) / 256, 256>>>(ei, batch);
    scan_local<<<N_SCANBLK, SCAN_B>>>();
    scan_sums<<<1, 64>>>();
    scan_finish<<<(N_NODES + 255) / 256, 256>>>();
    fill_kernel<<<(N_EDGES + 255) / 256, 256>>>(ei);

    agg1_kernel<<<(N_NODES * 32 + 255) / 256, 256>>>(x);
    gemm1_kernel<<<(N_NODES + 31) / 32, 256>>>(W1, b1);

    agg2_kernel<<<(N_NODES * 32 + 255) / 256, 256>>>();
    {
        dim3 grid((N_NODES + GM - 1) / GM, 256 / GN);
        gemm2_tc<<<grid, 256>>>(W2, b2);
    }

    pool_kernel<<<(N_NODES + 63) / 64, 256>>>(batch);
    head_kernel<<<N_GRAPHS, 128>>>(f1w, f1b, f2w, f2b, out);
}

// round 6
// speedup vs baseline: 1.8448x; 1.1392x over previous
#include <cuda_runtime.h>
#include <cuda_bf16.h>
#include <math.h>

#define N_NODES 50000
#define N_EDGES 800000
#define N_GRAPHS 256
#define D_HID 256
#define SCAN_B 1024
#define N_SCANBLK ((N_NODES + SCAN_B - 1) / SCAN_B)   // 49

// ---------------- scratch (device globals) ----------------------------------
__device__ float g_dinv[N_NODES];
__device__ int   g_deg[N_NODES];
__device__ int   g_rowptr[N_NODES + 1];
__device__ int   g_cursor[N_NODES];
__device__ int   g_colidx[N_EDGES];
__device__ int   g_scantmp[N_NODES];
__device__ int   g_blockoff[N_SCANBLK + 1];
__device__ int   g_blocksum[N_SCANBLK];
__device__ float g_aggx[(size_t)N_NODES * 16];
__device__ __nv_bfloat16 g_h1[(size_t)N_NODES * D_HID];   // bf16: halves agg2 gather traffic
__device__ float g_agg[(size_t)N_NODES * D_HID];
__device__ float g_h2[(size_t)N_NODES * D_HID];
__device__ float g_pool[N_GRAPHS * D_HID];
__device__ int   g_cnt[N_GRAPHS];
__device__ int   g_is32_ei;
__device__ int   g_is32_batch;

__device__ __forceinline__ float selu_f(float v) {
    const float a = 1.6732632423543772f, s = 1.0507009873554805f;
    return v > 0.f ? s * v : s * a * (expf(v) - 1.f);
}

__device__ __forceinline__ int load_idx(const void* p, long long i, int is32) {
    if (is32) return ((const int*)p)[i];
    return (int)((const long long*)p)[i];
}

__device__ __forceinline__ unsigned f2tf32(float f) {
    unsigned r;
    asm("cvt.rna.tf32.f32 %0, %1;" : "=r"(r) : "f"(f));
    return r;
}

// ---------------- init + dtype sniff (merged) --------------------------------
__global__ void init_kernel(const int* __restrict__ ei32, const int* __restrict__ b32) {
    int i = blockIdx.x * blockDim.x + threadIdx.x;
    if (i < N_NODES) g_deg[i] = 0;
    if (i < N_GRAPHS * D_HID) g_pool[i] = 0.f;
    if (i < N_GRAPHS) g_cnt[i] = 0;
    if (blockIdx.x == 0) {
        // 256 threads sample 8192 odd int32 words of each array (safe for both dtypes)
        int v = 0, w = 0;
        #pragma unroll
        for (int j = 0; j < 16; j++) {
            int idx = threadIdx.x + j * 256;
            v |= ei32[2 * idx + 1];
            w |= b32[2 * idx + 1];
        }
        __shared__ int s_ei, s_b;
        if (threadIdx.x == 0) { s_ei = 0; s_b = 0; }
        __syncthreads();
        if (v) s_ei = 1;
        if (w) s_b = 1;
        __syncthreads();
        if (threadIdx.x == 0) { g_is32_ei = s_ei; g_is32_batch = s_b; }
    }
}

__global__ void deg_count_kernel(const void* __restrict__ ei, const void* __restrict__ batch) {
    int i = blockIdx.x * blockDim.x + threadIdx.x;
    if (i < N_EDGES) atomicAdd(&g_deg[load_idx(ei, (long long)N_EDGES + i, g_is32_ei)], 1);
    if (i < N_NODES) atomicAdd(&g_cnt[load_idx(batch, i, g_is32_batch)], 1);
}

// ---------------- 3-phase exclusive scan of g_deg ----------------------------
__global__ void scan_local() {
    __shared__ int warp_sums[32];
    int b = blockIdx.x, t = threadIdx.x;
    int i = b * SCAN_B + t;
    int v = (i < N_NODES) ? g_deg[i] : 0;
    int x = v;
    #pragma unroll
    for (int off = 1; off < 32; off <<= 1) {
        int y = __shfl_up_sync(0xffffffffu, x, off);
        if ((t & 31) >= off) x += y;
    }
    if ((t & 31) == 31) warp_sums[t >> 5] = x;
    __syncthreads();
    if (t < 32) {
        int s = warp_sums[t];
        #pragma unroll
        for (int off = 1; off < 32; off <<= 1) {
            int y = __shfl_up_sync(0xffffffffu, s, off);
            if (t >= off) s += y;
        }
        warp_sums[t] = s;
    }
    __syncthreads();
    int inc = x + ((t >= 32) ? warp_sums[(t >> 5) - 1] : 0);
    if (i < N_NODES) g_scantmp[i] = inc;
    if (t == SCAN_B - 1) g_blocksum[b] = inc;
}

__global__ void scan_sums() {
    __shared__ int sh[64];
    int t = threadIdx.x;
    sh[t] = (t < N_SCANBLK) ? g_blocksum[t] : 0;
    __syncthreads();
    #pragma unroll
    for (int off = 1; off < 64; off <<= 1) {
        int y = (t >= off) ? sh[t - off] : 0;
        __syncthreads();
        sh[t] += y;
        __syncthreads();
    }
    if (t == 0) g_blockoff[0] = 0;
    g_blockoff[t + 1] = sh[t];
}

__global__ void scan_finish() {
    int i = blockIdx.x * blockDim.x + threadIdx.x;
    if (i < N_NODES) {
        int d = g_deg[i];
        int r = g_scantmp[i] - d + g_blockoff[i >> 10];
        g_rowptr[i] = r;
        g_cursor[i] = r;
        g_dinv[i] = rsqrtf((float)(d + 1));
    }
    if (i == 0) g_rowptr[N_NODES] = g_blockoff[N_SCANBLK];
}

__global__ void fill_kernel(const void* __restrict__ ei) {
    int e = blockIdx.x * blockDim.x + threadIdx.x;
    int is32 = g_is32_ei;
    if (e < N_EDGES) {
        int d = load_idx(ei, (long long)N_EDGES + e, is32);
        int p = atomicAdd(&g_cursor[d], 1);
        g_colidx[p] = load_idx(ei, e, is32);
    }
}

// ---------------- layer 1: 2 nodes per warp, 16 lanes each -------------------
__global__ void agg1_kernel(const float* __restrict__ x) {
    int gt = blockIdx.x * blockDim.x + threadIdx.x;
    int lane = threadIdx.x & 31;
    int w = (gt >> 5) * 2 + (lane >> 4);  // node id
    int f = lane & 15;                    // feature id
    if (w >= N_NODES) return;
    float di = g_dinv[w];
    float acc = 0.f;
    if (f < 14) acc = di * x[(size_t)w * 14 + f];
    int e0 = g_rowptr[w], e1 = g_rowptr[w + 1];
    for (int e = e0; e < e1; e++) {
        int s = g_colidx[e];
        float ds = g_dinv[s];
        if (f < 14) acc += ds * x[(size_t)s * 14 + f];
    }
    g_aggx[(size_t)w * 16 + f] = (f < 14) ? di * acc : 0.f;
}

__global__ void gemm1_kernel(const float* __restrict__ W1, const float* __restrict__ b1) {
    __shared__ __align__(16) float sx[32][16];
    int row0 = blockIdx.x * 32;
    int tid = threadIdx.x;  // 256
    #pragma unroll
    for (int it = 0; it < 2; it++) {
        int idx = tid + it * 256;
        int r = idx >> 4, c = idx & 15;
        int row = row0 + r;
        sx[r][c] = (row < N_NODES) ? g_aggx[(size_t)row * 16 + c] : 0.f;
    }
    __syncthreads();
    float w[14];
    #pragma unroll
    for (int k = 0; k < 14; k++) w[k] = W1[k * 256 + tid];
    float bj = b1[tid];
    for (int r = 0; r < 32; r++) {
        int row = row0 + r;
        if (row >= N_NODES) break;
        float acc = bj;
        #pragma unroll
        for (int k = 0; k < 14; k++) acc += sx[r][k] * w[k];
        g_h1[(size_t)row * 256 + tid] = __float2bfloat16(selu_f(acc));
    }
}

// ---------------- layer 2 aggregate: bf16 gather, fp32 accumulate ------------
__global__ void agg2_kernel() {
    int w = (blockIdx.x * blockDim.x + threadIdx.x) >> 5;
    int lane = threadIdx.x & 31;
    if (w >= N_NODES) return;
    float di = g_dinv[w];
    float acc[8];
    {
        const float4* self = (const float4*)(g_h1 + (size_t)w * 256);
        float4 raw = self[lane];
        const __nv_bfloat162* p = (const __nv_bfloat162*)&raw;
        #pragma unroll
        for (int q = 0; q < 4; q++) {
            float2 v = __bfloat1622float2(p[q]);
            acc[2 * q]     = di * v.x;
            acc[2 * q + 1] = di * v.y;
        }
    }
    int e0 = g_rowptr[w], e1 = g_rowptr[w + 1];
    for (int e = e0; e < e1; e++) {
        int s = g_colidx[e];
        float ds = g_dinv[s];
        const float4* sp = (const float4*)(g_h1 + (size_t)s * 256);
        float4 raw = sp[lane];
        const __nv_bfloat162* p = (const __nv_bfloat162*)&raw;
        #pragma unroll
        for (int q = 0; q < 4; q++) {
            float2 v = __bfloat1622float2(p[q]);
            acc[2 * q]     += ds * v.x;
            acc[2 * q + 1] += ds * v.y;
        }
    }
    float4* op = (float4*)(g_agg + (size_t)w * 256);
    op[2 * lane]     = make_float4(di * acc[0], di * acc[1], di * acc[2], di * acc[3]);
    op[2 * lane + 1] = make_float4(di * acc[4], di * acc[5], di * acc[6], di * acc[7]);
}

// ---------------- GEMM2 via tf32 tensor cores --------------------------------
#define GM 128
#define GN 128
#define GK 32
#define GS (GM + 4)

__global__ void __launch_bounds__(256, 2) gemm2_tc(const float* __restrict__ W,
                                                   const float* __restrict__ bias) {
    __shared__ unsigned As[GK][GS];
    __shared__ unsigned Bs[GK][GS];
    int m0 = blockIdx.x * GM, n0 = blockIdx.y * GN;
    int tid = threadIdx.x;
    int lane = tid & 31, warp = tid >> 5;
    int wm = (warp >> 1) * 32;
    int wn = (warp & 1) * 64;
    int g = lane >> 2, tg = lane & 3;

    float d[2][8][4];
    #pragma unroll
    for (int mi = 0; mi < 2; mi++)
        #pragma unroll
        for (int ni = 0; ni < 8; ni++)
            #pragma unroll
            for (int q = 0; q < 4; q++) d[mi][ni][q] = 0.f;

    for (int k0 = 0; k0 < 256; k0 += GK) {
        #pragma unroll
        for (int it = 0; it < 4; it++) {
            int idx = tid + it * 256;
            int row = idx >> 3;
            int c = (idx & 7) * 4;
            float4 av = make_float4(0.f, 0.f, 0.f, 0.f);
            if (m0 + row < N_NODES)
                av = *(const float4*)(g_agg + (size_t)(m0 + row) * 256 + k0 + c);
            As[c + 0][row] = f2tf32(av.x);
            As[c + 1][row] = f2tf32(av.y);
            As[c + 2][row] = f2tf32(av.z);
            As[c + 3][row] = f2tf32(av.w);
        }
        #pragma unroll
        for (int it = 0; it < 4; it++) {
            int idx = tid + it * 256;
            int kr = idx >> 5;
            int nc = (idx & 31) * 4;
            float4 bv = *(const float4*)(W + (size_t)(k0 + kr) * 256 + n0 + nc);
            Bs[kr][nc + 0] = f2tf32(bv.x);
            Bs[kr][nc + 1] = f2tf32(bv.y);
            Bs[kr][nc + 2] = f2tf32(bv.z);
            Bs[kr][nc + 3] = f2tf32(bv.w);
        }
        __syncthreads();

        #pragma unroll
        for (int kk = 0; kk < GK; kk += 8) {
            unsigned a[2][4], b[8][2];
            #pragma unroll
            for (int mi = 0; mi < 2; mi++) {
                int mb = wm + mi * 16;
                a[mi][0] = As[kk + tg][mb + g];
                a[mi][1] = As[kk + tg][mb + g + 8];
                a[mi][2] = As[kk + tg + 4][mb + g];
                a[mi][3] = As[kk + tg + 4][mb + g + 8];
            }
            #pragma unroll
            for (int ni = 0; ni < 8; ni++) {
                int nb = wn + ni * 8;
                b[ni][0] = Bs[kk + tg][nb + g];
                b[ni][1] = Bs[kk + tg + 4][nb + g];
            }
            #pragma unroll
            for (int mi = 0; mi < 2; mi++)
                #pragma unroll
                for (int ni = 0; ni < 8; ni++)
                    asm volatile(
                        "mma.sync.aligned.m16n8k8.row.col.f32.tf32.tf32.f32 "
                        "{%0,%1,%2,%3},{%4,%5,%6,%7},{%8,%9},{%0,%1,%2,%3};"
                        : "+f"(d[mi][ni][0]), "+f"(d[mi][ni][1]),
                          "+f"(d[mi][ni][2]), "+f"(d[mi][ni][3])
                        : "r"(a[mi][0]), "r"(a[mi][1]), "r"(a[mi][2]), "r"(a[mi][3]),
                          "r"(b[ni][0]), "r"(b[ni][1]));
        }
        __syncthreads();
    }

    #pragma unroll
    for (int mi = 0; mi < 2; mi++) {
        int r0 = m0 + wm + mi * 16 + g;
        #pragma unroll
        for (int ni = 0; ni < 8; ni++) {
            int col = n0 + wn + ni * 8 + 2 * tg;
            float bz0 = bias[col], bz1 = bias[col + 1];
            if (r0 < N_NODES) {
                float2 o = make_float2(selu_f(d[mi][ni][0] + bz0),
                                       selu_f(d[mi][ni][1] + bz1));
                *(float2*)(g_h2 + (size_t)r0 * 256 + col) = o;
            }
            int r1 = r0 + 8;
            if (r1 < N_NODES) {
                float2 o = make_float2(selu_f(d[mi][ni][2] + bz0),
                                       selu_f(d[mi][ni][3] + bz1));
                *(float2*)(g_h2 + (size_t)r1 * 256 + col) = o;
            }
        }
    }
}

// ---------------- pooling ----------------------------------------------------
__global__ void pool_kernel(const void* __restrict__ batch) {
    int c = threadIdx.x;  // 0..255
    int is32 = g_is32_batch;
    int n0 = blockIdx.x * 64;
    int n1 = n0 + 64;
    if (n1 > N_NODES) n1 = N_NODES;
    int cur = load_idx(batch, n0, is32);
    float acc = 0.f;
    for (int n = n0; n < n1; n++) {
        int g = load_idx(batch, n, is32);
        if (g != cur) {
            atomicAdd(&g_pool[cur * 256 + c], acc);
            acc = 0.f;
            cur = g;
        }
        acc += g_h2[(size_t)n * 256 + c];
    }
    atomicAdd(&g_pool[cur * 256 + c], acc);
}

// ---------------- head -------------------------------------------------------
__global__ void head_kernel(const float* __restrict__ fc1w, const float* __restrict__ fc1b,
                            const float* __restrict__ fc2w, const float* __restrict__ fc2b,
                            float* __restrict__ out) {
    __shared__ __align__(16) float sp[256];
    __shared__ __align__(16) float sg[128];
    __shared__ float slog[2];
    int g = blockIdx.x, t = threadIdx.x;  // 128 threads
    float c = fmaxf((float)g_cnt[g], 1.0f);
    for (int j = t; j < 256; j += 128) sp[j] = selu_f(g_pool[g * 256 + j] / c);
    __syncthreads();
    float acc = fc1b[t];
    for (int k = 0; k < 256; k++) acc += sp[k] * fc1w[k * 128 + t];
    sg[t] = selu_f(acc);
    __syncthreads();
    if (t < 2) {
        float a = fc2b[t];
        for (int k = 0; k < 128; k++) a += sg[k] * fc2w[k * 2 + t];
        slog[t] = a;
    }
    __syncthreads();
    if (t < 2) {
        float m = fmaxf(slog[0], slog[1]);
        float lse = m + logf(expf(slog[0] - m) + expf(slog[1] - m));
        out[g * 2 + t] = slog[t] - lse;
    }
}

// ---------------- launch -----------------------------------------------------
extern "C" void kernel_launch(void* const* d_in, const int* in_sizes, int n_in,
                              void* d_out, int out_size) {
    const float* x     = (const float*)d_in[0];
    const void*  ei    = d_in[1];
    const void*  batch = d_in[2];
    const float* W1  = (const float*)d_in[3];
    const float* b1  = (const float*)d_in[4];
    const float* W2  = (const float*)d_in[5];
    const float* b2  = (const float*)d_in[6];
    const float* f1w = (const float*)d_in[7];
    const float* f1b = (const float*)d_in[8];
    const float* f2w = (const float*)d_in[9];
    const float* f2b = (const float*)d_in[10];
    float* out = (float*)d_out;

    init_kernel<<<256, 256>>>((const int*)ei, (const int*)batch);
    deg_count_kernel<<<(N_EDGES + 255) / 256, 256>>>(ei, batch);
    scan_local<<<N_SCANBLK, SCAN_B>>>();
    scan_sums<<<1, 64>>>();
    scan_finish<<<(N_NODES + 255) / 256, 256>>>();
    fill_kernel<<<(N_EDGES + 255) / 256, 256>>>(ei);

    agg1_kernel<<<(N_NODES / 2 * 32 + 255) / 256, 256>>>(x);
    gemm1_kernel<<<(N_NODES + 31) / 32, 256>>>(W1, b1);

    agg2_kernel<<<(N_NODES * 32 + 255) / 256, 256>>>();
    {
        dim3 grid((N_NODES + GM - 1) / GM, 256 / GN);
        gemm2_tc<<<grid, 256>>>(W2, b2);
    }

    pool_kernel<<<(N_NODES + 63) / 64, 256>>>(batch);
    head_kernel<<<N_GRAPHS, 128>>>(f1w, f1b, f2w, f2b, out);
}

// round 8
// speedup vs baseline: 2.0207x; 1.0954x over previous
#include <cuda_runtime.h>
#include <cuda_bf16.h>
#include <math.h>

#define N_NODES 50000
#define N_EDGES 800000
#define N_GRAPHS 256
#define D_HID 256
#define SCAN_B 1024
#define N_SCANBLK ((N_NODES + SCAN_B - 1) / SCAN_B)   // 49

// ---------------- scratch (device globals) ----------------------------------
__device__ float g_dinv[N_NODES];
__device__ int   g_deg[N_NODES];
__device__ int   g_rowptr[N_NODES + 1];
__device__ int   g_cursor[N_NODES];
__device__ int   g_colidx[N_EDGES];
__device__ int   g_scantmp[N_NODES];
__device__ int   g_blockoff[N_SCANBLK + 1];
__device__ int   g_blocksum[N_SCANBLK];
__device__ float g_aggx[(size_t)N_NODES * 16];
__device__ __nv_bfloat16 g_h1[(size_t)N_NODES * D_HID];
__device__ float g_agg[(size_t)N_NODES * D_HID];
__device__ float g_pool[N_GRAPHS * D_HID];
__device__ int   g_cnt[N_GRAPHS];
__device__ int   g_is32_ei;
__device__ int   g_is32_batch;

__device__ __forceinline__ float selu_f(float v) {
    const float a = 1.6732632423543772f, s = 1.0507009873554805f;
    return v > 0.f ? s * v : s * a * (expf(v) - 1.f);
}

__device__ __forceinline__ int load_idx(const void* p, long long i, int is32) {
    if (is32) return ((const int*)p)[i];
    return (int)((const long long*)p)[i];
}

__device__ __forceinline__ unsigned f2tf32(float f) {
    unsigned r;
    asm("cvt.rna.tf32.f32 %0, %1;" : "=r"(r) : "f"(f));
    return r;
}

// ---------------- init + dtype sniff (merged) --------------------------------
__global__ void init_kernel(const int* __restrict__ ei32, const int* __restrict__ b32) {
    int i = blockIdx.x * blockDim.x + threadIdx.x;
    if (i < N_NODES) g_deg[i] = 0;
    if (i < N_GRAPHS * D_HID) g_pool[i] = 0.f;
    if (i < N_GRAPHS) g_cnt[i] = 0;
    if (blockIdx.x == 0) {
        int v = 0, w = 0;
        #pragma unroll
        for (int j = 0; j < 16; j++) {
            int idx = threadIdx.x + j * 256;
            v |= ei32[2 * idx + 1];
            w |= b32[2 * idx + 1];
        }
        __shared__ int s_ei, s_b;
        if (threadIdx.x == 0) { s_ei = 0; s_b = 0; }
        __syncthreads();
        if (v) s_ei = 1;
        if (w) s_b = 1;
        __syncthreads();
        if (threadIdx.x == 0) { g_is32_ei = s_ei; g_is32_batch = s_b; }
    }
}

__global__ void deg_count_kernel(const void* __restrict__ ei, const void* __restrict__ batch) {
    int i = blockIdx.x * blockDim.x + threadIdx.x;
    if (i < N_EDGES) atomicAdd(&g_deg[load_idx(ei, (long long)N_EDGES + i, g_is32_ei)], 1);
    if (i < N_NODES) atomicAdd(&g_cnt[load_idx(batch, i, g_is32_batch)], 1);
}

// ---------------- 3-phase exclusive scan of g_deg ----------------------------
__global__ void scan_local() {
    __shared__ int warp_sums[32];
    int b = blockIdx.x, t = threadIdx.x;
    int i = b * SCAN_B + t;
    int v = (i < N_NODES) ? g_deg[i] : 0;
    int x = v;
    #pragma unroll
    for (int off = 1; off < 32; off <<= 1) {
        int y = __shfl_up_sync(0xffffffffu, x, off);
        if ((t & 31) >= off) x += y;
    }
    if ((t & 31) == 31) warp_sums[t >> 5] = x;
    __syncthreads();
    if (t < 32) {
        int s = warp_sums[t];
        #pragma unroll
        for (int off = 1; off < 32; off <<= 1) {
            int y = __shfl_up_sync(0xffffffffu, s, off);
            if (t >= off) s += y;
        }
        warp_sums[t] = s;
    }
    __syncthreads();
    int inc = x + ((t >= 32) ? warp_sums[(t >> 5) - 1] : 0);
    if (i < N_NODES) g_scantmp[i] = inc;
    if (t == SCAN_B - 1) g_blocksum[b] = inc;
}

__global__ void scan_sums() {
    __shared__ int sh[64];
    int t = threadIdx.x;
    sh[t] = (t < N_SCANBLK) ? g_blocksum[t] : 0;
    __syncthreads();
    #pragma unroll
    for (int off = 1; off < 64; off <<= 1) {
        int y = (t >= off) ? sh[t - off] : 0;
        __syncthreads();
        sh[t] += y;
        __syncthreads();
    }
    if (t == 0) g_blockoff[0] = 0;
    g_blockoff[t + 1] = sh[t];
}

__global__ void scan_finish() {
    int i = blockIdx.x * blockDim.x + threadIdx.x;
    if (i < N_NODES) {
        int d = g_deg[i];
        int r = g_scantmp[i] - d + g_blockoff[i >> 10];
        g_rowptr[i] = r;
        g_cursor[i] = r;
        g_dinv[i] = rsqrtf((float)(d + 1));
    }
    if (i == 0) g_rowptr[N_NODES] = g_blockoff[N_SCANBLK];
}

__global__ void fill_kernel(const void* __restrict__ ei) {
    int e = blockIdx.x * blockDim.x + threadIdx.x;
    int is32 = g_is32_ei;
    if (e < N_EDGES) {
        int d = load_idx(ei, (long long)N_EDGES + e, is32);
        int p = atomicAdd(&g_cursor[d], 1);
        g_colidx[p] = load_idx(ei, e, is32);
    }
}

// ---------------- layer 1: 2 nodes per warp, 16 lanes each -------------------
__global__ void agg1_kernel(const float* __restrict__ x) {
    int gt = blockIdx.x * blockDim.x + threadIdx.x;
    int lane = threadIdx.x & 31;
    int w = (gt >> 5) * 2 + (lane >> 4);
    int f = lane & 15;
    if (w >= N_NODES) return;
    float di = g_dinv[w];
    float acc = 0.f;
    if (f < 14) acc = di * x[(size_t)w * 14 + f];
    int e0 = g_rowptr[w], e1 = g_rowptr[w + 1];
    for (int e = e0; e < e1; e++) {
        int s = g_colidx[e];
        float ds = g_dinv[s];
        if (f < 14) acc += ds * x[(size_t)s * 14 + f];
    }
    g_aggx[(size_t)w * 16 + f] = (f < 14) ? di * acc : 0.f;
}

__global__ void gemm1_kernel(const float* __restrict__ W1, const float* __restrict__ b1) {
    __shared__ __align__(16) float sx[32][16];
    int row0 = blockIdx.x * 32;
    int tid = threadIdx.x;  // 256
    #pragma unroll
    for (int it = 0; it < 2; it++) {
        int idx = tid + it * 256;
        int r = idx >> 4, c = idx & 15;
        int row = row0 + r;
        sx[r][c] = (row < N_NODES) ? g_aggx[(size_t)row * 16 + c] : 0.f;
    }
    __syncthreads();
    float w[14];
    #pragma unroll
    for (int k = 0; k < 14; k++) w[k] = W1[k * 256 + tid];
    float bj = b1[tid];
    for (int r = 0; r < 32; r++) {
        int row = row0 + r;
        if (row >= N_NODES) break;
        float acc = bj;
        #pragma unroll
        for (int k = 0; k < 14; k++) acc += sx[r][k] * w[k];
        g_h1[(size_t)row * 256 + tid] = __float2bfloat16(selu_f(acc));
    }
}

// ---------------- layer 2 aggregate: bf16 gather, unroll-2, fp32 accum -------
__global__ void agg2_kernel() {
    int w = (blockIdx.x * blockDim.x + threadIdx.x) >> 5;
    int lane = threadIdx.x & 31;
    if (w >= N_NODES) return;
    float di = g_dinv[w];
    float acc[8];
    {
        float4 raw = ((const float4*)(g_h1 + (size_t)w * 256))[lane];
        const __nv_bfloat162* p = (const __nv_bfloat162*)&raw;
        #pragma unroll
        for (int q = 0; q < 4; q++) {
            float2 v = __bfloat1622float2(p[q]);
            acc[2 * q]     = di * v.x;
            acc[2 * q + 1] = di * v.y;
        }
    }
    int e0 = g_rowptr[w], e1 = g_rowptr[w + 1];
    int e = e0;
    for (; e + 1 < e1; e += 2) {
        int s0 = g_colidx[e], s1 = g_colidx[e + 1];
        float ds0 = g_dinv[s0], ds1 = g_dinv[s1];
        float4 r0 = ((const float4*)(g_h1 + (size_t)s0 * 256))[lane];
        float4 r1 = ((const float4*)(g_h1 + (size_t)s1 * 256))[lane];
        const __nv_bfloat162* p0 = (const __nv_bfloat162*)&r0;
        const __nv_bfloat162* p1 = (const __nv_bfloat162*)&r1;
        #pragma unroll
        for (int q = 0; q < 4; q++) {
            float2 v0 = __bfloat1622float2(p0[q]);
            float2 v1 = __bfloat1622float2(p1[q]);
            acc[2 * q]     += ds0 * v0.x + ds1 * v1.x;
            acc[2 * q + 1] += ds0 * v0.y + ds1 * v1.y;
        }
    }
    if (e < e1) {
        int s = g_colidx[e];
        float ds = g_dinv[s];
        float4 raw = ((const float4*)(g_h1 + (size_t)s * 256))[lane];
        const __nv_bfloat162* p = (const __nv_bfloat162*)&raw;
        #pragma unroll
        for (int q = 0; q < 4; q++) {
            float2 v = __bfloat1622float2(p[q]);
            acc[2 * q]     += ds * v.x;
            acc[2 * q + 1] += ds * v.y;
        }
    }
    float4* op = (float4*)(g_agg + (size_t)w * 256);
    op[2 * lane]     = make_float4(di * acc[0], di * acc[1], di * acc[2], di * acc[3]);
    op[2 * lane + 1] = make_float4(di * acc[4], di * acc[5], di * acc[6], di * acc[7]);
}

// ---------------- GEMM2 (tf32 TC) with fused bias+selu+pool ------------------
// h2 is never materialized: pooled sums go straight to g_pool.
#define GM 128
#define GN 128
#define GK 32
#define GS (GM + 4)

__global__ void __launch_bounds__(256, 2) gemm2_tc(const float* __restrict__ W,
                                                   const float* __restrict__ bias,
                                                   const void* __restrict__ batch) {
    __shared__ unsigned As[GK][GS];
    __shared__ unsigned Bs[GK][GS];
    int m0 = blockIdx.x * GM, n0 = blockIdx.y * GN;
    int tid = threadIdx.x;
    int lane = tid & 31, warp = tid >> 5;
    int wm = (warp >> 1) * 32;
    int wn = (warp & 1) * 64;
    int g = lane >> 2, tg = lane & 3;

    float d[2][8][4];
    #pragma unroll
    for (int mi = 0; mi < 2; mi++)
        #pragma unroll
        for (int ni = 0; ni < 8; ni++)
            #pragma unroll
            for (int q = 0; q < 4; q++) d[mi][ni][q] = 0.f;

    for (int k0 = 0; k0 < 256; k0 += GK) {
        #pragma unroll
        for (int it = 0; it < 4; it++) {
            int idx = tid + it * 256;
            int row = idx >> 3;
            int c = (idx & 7) * 4;
            float4 av = make_float4(0.f, 0.f, 0.f, 0.f);
            if (m0 + row < N_NODES)
                av = *(const float4*)(g_agg + (size_t)(m0 + row) * 256 + k0 + c);
            As[c + 0][row] = f2tf32(av.x);
            As[c + 1][row] = f2tf32(av.y);
            As[c + 2][row] = f2tf32(av.z);
            As[c + 3][row] = f2tf32(av.w);
        }
        #pragma unroll
        for (int it = 0; it < 4; it++) {
            int idx = tid + it * 256;
            int kr = idx >> 5;
            int nc = (idx & 31) * 4;
            float4 bv = *(const float4*)(W + (size_t)(k0 + kr) * 256 + n0 + nc);
            Bs[kr][nc + 0] = f2tf32(bv.x);
            Bs[kr][nc + 1] = f2tf32(bv.y);
            Bs[kr][nc + 2] = f2tf32(bv.z);
            Bs[kr][nc + 3] = f2tf32(bv.w);
        }
        __syncthreads();

        #pragma unroll
        for (int kk = 0; kk < GK; kk += 8) {
            unsigned a[2][4], b[8][2];
            #pragma unroll
            for (int mi = 0; mi < 2; mi++) {
                int mb = wm + mi * 16;
                a[mi][0] = As[kk + tg][mb + g];
                a[mi][1] = As[kk + tg][mb + g + 8];
                a[mi][2] = As[kk + tg + 4][mb + g];
                a[mi][3] = As[kk + tg + 4][mb + g + 8];
            }
            #pragma unroll
            for (int ni = 0; ni < 8; ni++) {
                int nb = wn + ni * 8;
                b[ni][0] = Bs[kk + tg][nb + g];
                b[ni][1] = Bs[kk + tg + 4][nb + g];
            }
            #pragma unroll
            for (int mi = 0; mi < 2; mi++)
                #pragma unroll
                for (int ni = 0; ni < 8; ni++)
                    asm volatile(
                        "mma.sync.aligned.m16n8k8.row.col.f32.tf32.tf32.f32 "
                        "{%0,%1,%2,%3},{%4,%5,%6,%7},{%8,%9},{%0,%1,%2,%3};"
                        : "+f"(d[mi][ni][0]), "+f"(d[mi][ni][1]),
                          "+f"(d[mi][ni][2]), "+f"(d[mi][ni][3])
                        : "r"(a[mi][0]), "r"(a[mi][1]), "r"(a[mi][2]), "r"(a[mi][3]),
                          "r"(b[ni][0]), "r"(b[ni][1]));
        }
        __syncthreads();
    }

    // ---- fused epilogue: bias + selu + segmented pool -> g_pool atomics ----
    // lane = g*4+tg; the 8 lanes sharing a column pair differ only in g,
    // reached exactly by xor offsets {4,8,16}; leader g==0 holds the 16-row sum.
    int is32 = g_is32_batch;
    #pragma unroll
    for (int mi = 0; mi < 2; mi++) {
        int rbase = m0 + wm + mi * 16;   // fragment group covers rows rbase..rbase+15
        int r0 = rbase + g;
        int r1 = r0 + 8;
        bool full = (rbase + 15) < N_NODES;
        int gid_first = load_idx(batch, full ? rbase : (N_NODES - 1), is32);
        int gid_last  = load_idx(batch, full ? (rbase + 15) : (N_NODES - 1), is32);
        bool uniform = full && (gid_first == gid_last);   // warp-uniform predicate
        #pragma unroll
        for (int ni = 0; ni < 8; ni++) {
            int c0 = n0 + wn + ni * 8 + 2 * tg;
            float bz0 = bias[c0], bz1 = bias[c0 + 1];
            float v00 = selu_f(d[mi][ni][0] + bz0);
            float v01 = selu_f(d[mi][ni][1] + bz1);
            float v10 = selu_f(d[mi][ni][2] + bz0);
            float v11 = selu_f(d[mi][ni][3] + bz1);
            if (uniform) {
                float s0 = v00 + v10;   // both rows same graph
                float s1 = v01 + v11;
                #pragma unroll
                for (int off = 4; off < 32; off <<= 1) {
                    s0 += __shfl_xor_sync(0xffffffffu, s0, off);
                    s1 += __shfl_xor_sync(0xffffffffu, s1, off);
                }
                if (g == 0) {
                    atomicAdd(&g_pool[gid_first * 256 + c0], s0);
                    atomicAdd(&g_pool[gid_first * 256 + c0 + 1], s1);
                }
            } else {
                if (r0 < N_NODES) {
                    int gr = load_idx(batch, r0, is32);
                    atomicAdd(&g_pool[gr * 256 + c0], v00);
                    atomicAdd(&g_pool[gr * 256 + c0 + 1], v01);
                }
                if (r1 < N_NODES) {
                    int gr = load_idx(batch, r1, is32);
                    atomicAdd(&g_pool[gr * 256 + c0], v10);
                    atomicAdd(&g_pool[gr * 256 + c0 + 1], v11);
                }
            }
        }
    }
}

// ---------------- head -------------------------------------------------------
__global__ void head_kernel(const float* __restrict__ fc1w, const float* __restrict__ fc1b,
                            const float* __restrict__ fc2w, const float* __restrict__ fc2b,
                            float* __restrict__ out) {
    __shared__ __align__(16) float sp[256];
    __shared__ __align__(16) float sg[128];
    __shared__ float slog[2];
    int g = blockIdx.x, t = threadIdx.x;  // 128 threads
    float c = fmaxf((float)g_cnt[g], 1.0f);
    for (int j = t; j < 256; j += 128) sp[j] = selu_f(g_pool[g * 256 + j] / c);
    __syncthreads();
    float acc = fc1b[t];
    for (int k = 0; k < 256; k++) acc += sp[k] * fc1w[k * 128 + t];
    sg[t] = selu_f(acc);
    __syncthreads();
    if (t < 2) {
        float a = fc2b[t];
        for (int k = 0; k < 128; k++) a += sg[k] * fc2w[k * 2 + t];
        slog[t] = a;
    }
    __syncthreads();
    if (t < 2) {
        float m = fmaxf(slog[0], slog[1]);
        float lse = m + logf(expf(slog[0] - m) + expf(slog[1] - m));
        out[g * 2 + t] = slog[t] - lse;
    }
}

// ---------------- launch -----------------------------------------------------
extern "C" void kernel_launch(void* const* d_in, const int* in_sizes, int n_in,
                              void* d_out, int out_size) {
    const float* x     = (const float*)d_in[0];
    const void*  ei    = d_in[1];
    const void*  batch = d_in[2];
    const float* W1  = (const float*)d_in[3];
    const float* b1  = (const float*)d_in[4];
    const float* W2  = (const float*)d_in[5];
    const float* b2  = (const float*)d_in[6];
    const float* f1w = (const float*)d_in[7];
    const float* f1b = (const float*)d_in[8];
    const float* f2w = (const float*)d_in[9];
    const float* f2b = (const float*)d_in[10];
    float* out = (float*)d_out;

    init_kernel<<<256, 256>>>((const int*)ei, (const int*)batch);
    deg_count_kernel<<<(N_EDGES + 255) / 256, 256>>>(ei, batch);
    scan_local<<<N_SCANBLK, SCAN_B>>>();
    scan_sums<<<1, 64>>>();
    scan_finish<<<(N_NODES + 255) / 256, 256>>>();
    fill_kernel<<<(N_EDGES + 255) / 256, 256>>>(ei);

    agg1_kernel<<<(N_NODES / 2 * 32 + 255) / 256, 256>>>(x);
    gemm1_kernel<<<(N_NODES + 31) / 32, 256>>>(W1, b1);

    agg2_kernel<<<(N_NODES * 32 + 255) / 256, 256>>>();
    {
        dim3 grid((N_NODES + GM - 1) / GM, 256 / GN);
        gemm2_tc<<<grid, 256>>>(W2, b2, batch);
    }

    head_kernel<<<N_GRAPHS, 128>>>(f1w, f1b, f2w, f2b, out);
}

// round 9
// speedup vs baseline: 2.1459x; 1.0620x over previous
#include <cuda_runtime.h>
#include <cuda_bf16.h>
#include <math.h>

#define N_NODES 50000
#define N_EDGES 800000
#define N_GRAPHS 256
#define D_HID 256
#define SCAN_B 1024
#define N_SCANBLK ((N_NODES + SCAN_B - 1) / SCAN_B)   // 49

// ---------------- scratch (device globals) ----------------------------------
__device__ float g_dinv[N_NODES];
__device__ int   g_deg[N_NODES];
__device__ int   g_rowptr[N_NODES + 1];
__device__ int   g_cursor[N_NODES];
__device__ int   g_colidx[N_EDGES];
__device__ unsigned long long g_scanstate[N_SCANBLK];  // flag<<32 | sum
__device__ int   g_ticket;
__device__ __nv_bfloat16 g_h1[(size_t)N_NODES * D_HID];
__device__ __nv_bfloat16 g_agg[(size_t)N_NODES * D_HID];  // bf16 (fp32-accumulated)
__device__ float g_pool[N_GRAPHS * D_HID];
__device__ int   g_cnt[N_GRAPHS];
__device__ int   g_is32_ei;
__device__ int   g_is32_batch;

__device__ __forceinline__ float selu_f(float v) {
    const float a = 1.6732632423543772f, s = 1.0507009873554805f;
    return v > 0.f ? s * v : s * a * (expf(v) - 1.f);
}

__device__ __forceinline__ int load_idx(const void* p, long long i, int is32) {
    if (is32) return ((const int*)p)[i];
    return (int)((const long long*)p)[i];
}

__device__ __forceinline__ unsigned f2tf32(float f) {
    unsigned r;
    asm("cvt.rna.tf32.f32 %0, %1;" : "=r"(r) : "f"(f));
    return r;
}

// ---------------- init + dtype sniff (merged) --------------------------------
__global__ void init_kernel(const int* __restrict__ ei32, const int* __restrict__ b32) {
    int i = blockIdx.x * blockDim.x + threadIdx.x;
    if (i < N_NODES) g_deg[i] = 0;
    if (i < N_GRAPHS * D_HID) g_pool[i] = 0.f;
    if (i < N_GRAPHS) g_cnt[i] = 0;
    if (i < N_SCANBLK) g_scanstate[i] = 0ULL;
    if (i == 0) g_ticket = 0;
    if (blockIdx.x == 0) {
        int v = 0, w = 0;
        #pragma unroll
        for (int j = 0; j < 16; j++) {
            int idx = threadIdx.x + j * 256;
            v |= ei32[2 * idx + 1];
            w |= b32[2 * idx + 1];
        }
        __shared__ int s_ei, s_b;
        if (threadIdx.x == 0) { s_ei = 0; s_b = 0; }
        __syncthreads();
        if (v) s_ei = 1;
        if (w) s_b = 1;
        __syncthreads();
        if (threadIdx.x == 0) { g_is32_ei = s_ei; g_is32_batch = s_b; }
    }
}

__global__ void deg_count_kernel(const void* __restrict__ ei, const void* __restrict__ batch) {
    int i = blockIdx.x * blockDim.x + threadIdx.x;
    if (i < N_EDGES) atomicAdd(&g_deg[load_idx(ei, (long long)N_EDGES + i, g_is32_ei)], 1);
    if (i < N_NODES) atomicAdd(&g_cnt[load_idx(batch, i, g_is32_batch)], 1);
}

// ------- single-kernel decoupled-lookback scan (+cursor+dinv init) -----------
__global__ void __launch_bounds__(SCAN_B) scan_one() {
    __shared__ int warp_sums[32];
    __shared__ int s_bid, s_exc;
    int t = threadIdx.x;
    if (t == 0) s_bid = atomicAdd(&g_ticket, 1);
    __syncthreads();
    int b = s_bid;
    int i = b * SCAN_B + t;
    int v = (i < N_NODES) ? g_deg[i] : 0;
    int x = v;
    #pragma unroll
    for (int off = 1; off < 32; off <<= 1) {
        int y = __shfl_up_sync(0xffffffffu, x, off);
        if ((t & 31) >= off) x += y;
    }
    if ((t & 31) == 31) warp_sums[t >> 5] = x;
    __syncthreads();
    if (t < 32) {
        int s = warp_sums[t];
        #pragma unroll
        for (int off = 1; off < 32; off <<= 1) {
            int y = __shfl_up_sync(0xffffffffu, s, off);
            if (t >= off) s += y;
        }
        warp_sums[t] = s;
    }
    __syncthreads();
    int inc = x + ((t >= 32) ? warp_sums[(t >> 5) - 1] : 0);

    if (t == 0) {
        int total = warp_sums[31];
        if (b == 0) {
            atomicExch(&g_scanstate[0], (2ULL << 32) | (unsigned)total);
            s_exc = 0;
        } else {
            atomicExch(&g_scanstate[b], (1ULL << 32) | (unsigned)total);
            int exc = 0;
            int j = b - 1;
            while (true) {
                unsigned long long st;
                do { st = atomicAdd(&g_scanstate[j], 0ULL); } while ((st >> 32) == 0ULL);
                exc += (int)(unsigned)st;
                if ((st >> 32) == 2ULL) break;
                j--;
            }
            atomicExch(&g_scanstate[b], (2ULL << 32) | (unsigned)(total + exc));
            s_exc = exc;
        }
    }
    __syncthreads();
    int exc = s_exc;
    int r = exc + inc - v;   // exclusive prefix
    if (i < N_NODES) {
        g_rowptr[i] = r;
        g_cursor[i] = r;
        g_dinv[i] = rsqrtf((float)(v + 1));
    }
    if (i == N_NODES - 1) g_rowptr[N_NODES] = exc + inc;
}

__global__ void fill_kernel(const void* __restrict__ ei) {
    int e = blockIdx.x * blockDim.x + threadIdx.x;
    int is32 = g_is32_ei;
    if (e < N_EDGES) {
        int d = load_idx(ei, (long long)N_EDGES + e, is32);
        int p = atomicAdd(&g_cursor[d], 1);
        g_colidx[p] = load_idx(ei, e, is32);
    }
}

// ------- layer 1 fused: aggregate x into smem, then GEMM ---------------------
__global__ void gemm1_fused(const float* __restrict__ x,
                            const float* __restrict__ W1, const float* __restrict__ b1) {
    __shared__ __align__(16) float sx[32][16];
    int row0 = blockIdx.x * 32;
    int tid = threadIdx.x;  // 256
    int warp = tid >> 5, lane = tid & 31;
    int f = lane & 15;
    // phase 1: each warp aggregates 4 rows (2 at a time, 16 lanes per row)
    #pragma unroll
    for (int pair = 0; pair < 2; pair++) {
        int r = warp * 4 + pair * 2 + (lane >> 4);
        int row = row0 + r;
        float out = 0.f;
        if (row < N_NODES) {
            float di = g_dinv[row];
            float acc = 0.f;
            if (f < 14) acc = di * x[(size_t)row * 14 + f];
            int e0 = g_rowptr[row], e1 = g_rowptr[row + 1];
            for (int e = e0; e < e1; e++) {
                int s = g_colidx[e];
                float ds = g_dinv[s];
                if (f < 14) acc += ds * x[(size_t)s * 14 + f];
            }
            out = (f < 14) ? di * acc : 0.f;
        }
        sx[r][f] = out;
    }
    __syncthreads();
    // phase 2: [32,14] @ [14,256] + bias + selu -> bf16 h1
    float w[14];
    #pragma unroll
    for (int k = 0; k < 14; k++) w[k] = W1[k * 256 + tid];
    float bj = b1[tid];
    for (int r = 0; r < 32; r++) {
        int row = row0 + r;
        if (row >= N_NODES) break;
        float acc = bj;
        #pragma unroll
        for (int k = 0; k < 14; k++) acc += sx[r][k] * w[k];
        g_h1[(size_t)row * 256 + tid] = __float2bfloat16(selu_f(acc));
    }
}

// ------- layer 2 aggregate: bf16 gather, unroll-2, fp32 accum, bf16 out ------
__global__ void agg2_kernel() {
    int w = (blockIdx.x * blockDim.x + threadIdx.x) >> 5;
    int lane = threadIdx.x & 31;
    if (w >= N_NODES) return;
    float di = g_dinv[w];
    float acc[8];
    {
        float4 raw = ((const float4*)(g_h1 + (size_t)w * 256))[lane];
        const __nv_bfloat162* p = (const __nv_bfloat162*)&raw;
        #pragma unroll
        for (int q = 0; q < 4; q++) {
            float2 v = __bfloat1622float2(p[q]);
            acc[2 * q]     = di * v.x;
            acc[2 * q + 1] = di * v.y;
        }
    }
    int e0 = g_rowptr[w], e1 = g_rowptr[w + 1];
    int e = e0;
    for (; e + 1 < e1; e += 2) {
        int s0 = g_colidx[e], s1 = g_colidx[e + 1];
        float ds0 = g_dinv[s0], ds1 = g_dinv[s1];
        float4 r0 = ((const float4*)(g_h1 + (size_t)s0 * 256))[lane];
        float4 r1 = ((const float4*)(g_h1 + (size_t)s1 * 256))[lane];
        const __nv_bfloat162* p0 = (const __nv_bfloat162*)&r0;
        const __nv_bfloat162* p1 = (const __nv_bfloat162*)&r1;
        #pragma unroll
        for (int q = 0; q < 4; q++) {
            float2 v0 = __bfloat1622float2(p0[q]);
            float2 v1 = __bfloat1622float2(p1[q]);
            acc[2 * q]     += ds0 * v0.x + ds1 * v1.x;
            acc[2 * q + 1] += ds0 * v0.y + ds1 * v1.y;
        }
    }
    if (e < e1) {
        int s = g_colidx[e];
        float ds = g_dinv[s];
        float4 raw = ((const float4*)(g_h1 + (size_t)s * 256))[lane];
        const __nv_bfloat162* p = (const __nv_bfloat162*)&raw;
        #pragma unroll
        for (int q = 0; q < 4; q++) {
            float2 v = __bfloat1622float2(p[q]);
            acc[2 * q]     += ds * v.x;
            acc[2 * q + 1] += ds * v.y;
        }
    }
    __nv_bfloat162 h[4];
    #pragma unroll
    for (int q = 0; q < 4; q++)
        h[q] = __floats2bfloat162_rn(di * acc[2 * q], di * acc[2 * q + 1]);
    ((float4*)(g_agg + (size_t)w * 256))[lane] = *(float4*)h;
}

// ---------------- GEMM2 (tf32 TC, bf16 A) with fused bias+selu+pool ----------
#define GM 128
#define GN 128
#define GK 32
#define GS (GM + 4)

__global__ void __launch_bounds__(256, 2) gemm2_tc(const float* __restrict__ W,
                                                   const float* __restrict__ bias,
                                                   const void* __restrict__ batch) {
    __shared__ unsigned As[GK][GS];
    __shared__ unsigned Bs[GK][GS];
    int m0 = blockIdx.x * GM, n0 = blockIdx.y * GN;
    int tid = threadIdx.x;
    int lane = tid & 31, warp = tid >> 5;
    int wm = (warp >> 1) * 32;
    int wn = (warp & 1) * 64;
    int g = lane >> 2, tg = lane & 3;

    float d[2][8][4];
    #pragma unroll
    for (int mi = 0; mi < 2; mi++)
        #pragma unroll
        for (int ni = 0; ni < 8; ni++)
            #pragma unroll
            for (int q = 0; q < 4; q++) d[mi][ni][q] = 0.f;

    for (int k0 = 0; k0 < 256; k0 += GK) {
        // stage A: bf16 -> tf32 (exact), [k][m] layout
        #pragma unroll
        for (int it = 0; it < 2; it++) {
            int idx = tid + it * 256;        // 0..511
            int row = idx >> 2;              // 0..127
            int c = (idx & 3) * 8;           // 0,8,16,24
            float4 raw = make_float4(0.f, 0.f, 0.f, 0.f);
            if (m0 + row < N_NODES)
                raw = *(const float4*)(g_agg + (size_t)(m0 + row) * 256 + k0 + c);
            const __nv_bfloat162* p = (const __nv_bfloat162*)&raw;
            #pragma unroll
            for (int q = 0; q < 4; q++) {
                float2 v = __bfloat1622float2(p[q]);
                As[c + 2 * q][row]     = f2tf32(v.x);
                As[c + 2 * q + 1][row] = f2tf32(v.y);
            }
        }
        #pragma unroll
        for (int it = 0; it < 4; it++) {
            int idx = tid + it * 256;
            int kr = idx >> 5;
            int nc = (idx & 31) * 4;
            float4 bv = *(const float4*)(W + (size_t)(k0 + kr) * 256 + n0 + nc);
            Bs[kr][nc + 0] = f2tf32(bv.x);
            Bs[kr][nc + 1] = f2tf32(bv.y);
            Bs[kr][nc + 2] = f2tf32(bv.z);
            Bs[kr][nc + 3] = f2tf32(bv.w);
        }
        __syncthreads();

        #pragma unroll
        for (int kk = 0; kk < GK; kk += 8) {
            unsigned a[2][4], b[8][2];
            #pragma unroll
            for (int mi = 0; mi < 2; mi++) {
                int mb = wm + mi * 16;
                a[mi][0] = As[kk + tg][mb + g];
                a[mi][1] = As[kk + tg][mb + g + 8];
                a[mi][2] = As[kk + tg + 4][mb + g];
                a[mi][3] = As[kk + tg + 4][mb + g + 8];
            }
            #pragma unroll
            for (int ni = 0; ni < 8; ni++) {
                int nb = wn + ni * 8;
                b[ni][0] = Bs[kk + tg][nb + g];
                b[ni][1] = Bs[kk + tg + 4][nb + g];
            }
            #pragma unroll
            for (int mi = 0; mi < 2; mi++)
                #pragma unroll
                for (int ni = 0; ni < 8; ni++)
                    asm volatile(
                        "mma.sync.aligned.m16n8k8.row.col.f32.tf32.tf32.f32 "
                        "{%0,%1,%2,%3},{%4,%5,%6,%7},{%8,%9},{%0,%1,%2,%3};"
                        : "+f"(d[mi][ni][0]), "+f"(d[mi][ni][1]),
                          "+f"(d[mi][ni][2]), "+f"(d[mi][ni][3])
                        : "r"(a[mi][0]), "r"(a[mi][1]), "r"(a[mi][2]), "r"(a[mi][3]),
                          "r"(b[ni][0]), "r"(b[ni][1]));
        }
        __syncthreads();
    }

    // ---- fused epilogue: bias + selu + segmented pool -> g_pool atomics ----
    int is32 = g_is32_batch;
    #pragma unroll
    for (int mi = 0; mi < 2; mi++) {
        int rbase = m0 + wm + mi * 16;
        int r0 = rbase + g;
        int r1 = r0 + 8;
        bool full = (rbase + 15) < N_NODES;
        int gid_first = load_idx(batch, full ? rbase : (N_NODES - 1), is32);
        int gid_last  = load_idx(batch, full ? (rbase + 15) : (N_NODES - 1), is32);
        bool uniform = full && (gid_first == gid_last);
        #pragma unroll
        for (int ni = 0; ni < 8; ni++) {
            int c0 = n0 + wn + ni * 8 + 2 * tg;
            float bz0 = bias[c0], bz1 = bias[c0 + 1];
            float v00 = selu_f(d[mi][ni][0] + bz0);
            float v01 = selu_f(d[mi][ni][1] + bz1);
            float v10 = selu_f(d[mi][ni][2] + bz0);
            float v11 = selu_f(d[mi][ni][3] + bz1);
            if (uniform) {
                float s0 = v00 + v10;
                float s1 = v01 + v11;
                #pragma unroll
                for (int off = 4; off < 32; off <<= 1) {
                    s0 += __shfl_xor_sync(0xffffffffu, s0, off);
                    s1 += __shfl_xor_sync(0xffffffffu, s1, off);
                }
                if (g == 0) {
                    atomicAdd(&g_pool[gid_first * 256 + c0], s0);
                    atomicAdd(&g_pool[gid_first * 256 + c0 + 1], s1);
                }
            } else {
                if (r0 < N_NODES) {
                    int gr = load_idx(batch, r0, is32);
                    atomicAdd(&g_pool[gr * 256 + c0], v00);
                    atomicAdd(&g_pool[gr * 256 + c0 + 1], v01);
                }
                if (r1 < N_NODES) {
                    int gr = load_idx(batch, r1, is32);
                    atomicAdd(&g_pool[gr * 256 + c0], v10);
                    atomicAdd(&g_pool[gr * 256 + c0 + 1], v11);
                }
            }
        }
    }
}

// ---------------- head -------------------------------------------------------
__global__ void head_kernel(const float* __restrict__ fc1w, const float* __restrict__ fc1b,
                            const float* __restrict__ fc2w, const float* __restrict__ fc2b,
                            float* __restrict__ out) {
    __shared__ __align__(16) float sp[256];
    __shared__ __align__(16) float sg[128];
    __shared__ float slog[2];
    int g = blockIdx.x, t = threadIdx.x;  // 128 threads
    float c = fmaxf((float)g_cnt[g], 1.0f);
    for (int j = t; j < 256; j += 128) sp[j] = selu_f(g_pool[g * 256 + j] / c);
    __syncthreads();
    float acc = fc1b[t];
    for (int k = 0; k < 256; k++) acc += sp[k] * fc1w[k * 128 + t];
    sg[t] = selu_f(acc);
    __syncthreads();
    if (t < 2) {
        float a = fc2b[t];
        for (int k = 0; k < 128; k++) a += sg[k] * fc2w[k * 2 + t];
        slog[t] = a;
    }
    __syncthreads();
    if (t < 2) {
        float m = fmaxf(slog[0], slog[1]);
        float lse = m + logf(expf(slog[0] - m) + expf(slog[1] - m));
        out[g * 2 + t] = slog[t] - lse;
    }
}

// ---------------- launch -----------------------------------------------------
extern "C" void kernel_launch(void* const* d_in, const int* in_sizes, int n_in,
                              void* d_out, int out_size) {
    const float* x     = (const float*)d_in[0];
    const void*  ei    = d_in[1];
    const void*  batch = d_in[2];
    const float* W1  = (const float*)d_in[3];
    const float* b1  = (const float*)d_in[4];
    const float* W2  = (const float*)d_in[5];
    const float* b2  = (const float*)d_in[6];
    const float* f1w = (const float*)d_in[7];
    const float* f1b = (const float*)d_in[8];
    const float* f2w = (const float*)d_in[9];
    const float* f2b = (const float*)d_in[10];
    float* out = (float*)d_out;

    init_kernel<<<256, 256>>>((const int*)ei, (const int*)batch);
    deg_count_kernel<<<(N_EDGES + 255) / 256, 256>>>(ei, batch);
    scan_one<<<N_SCANBLK, SCAN_B>>>();
    fill_kernel<<<(N_EDGES + 255) / 256, 256>>>(ei);

    gemm1_fused<<<(N_NODES + 31) / 32, 256>>>(x, W1, b1);

    agg2_kernel<<<(N_NODES * 32 + 255) / 256, 256>>>();
    {
        dim3 grid((N_NODES + GM - 1) / GM, 256 / GN);
        gemm2_tc<<<grid, 256>>>(W2, b2, batch);
    }

    head_kernel<<<N_GRAPHS, 128>>>(f1w, f1b, f2w, f2b, out);
}

// round 10
// speedup vs baseline: 2.1891x; 1.0201x over previous
#include <cuda_runtime.h>
#include <cuda_bf16.h>
#include <math.h>

#define N_NODES 50000
#define N_EDGES 800000
#define N_GRAPHS 256
#define D_HID 256
#define SCAN_B 1024
#define N_SCANBLK ((N_NODES + SCAN_B - 1) / SCAN_B)   // 49

// ---------------- scratch (device globals) ----------------------------------
__device__ float g_dinv[N_NODES];
__device__ int   g_deg[N_NODES];
__device__ int   g_rowptr[N_NODES + 1];
__device__ int   g_cursor[N_NODES];
__device__ int   g_colidx[N_EDGES];
__device__ unsigned long long g_scanstate[N_SCANBLK];  // flag<<32 | sum
__device__ int   g_ticket;
__device__ __nv_bfloat16 g_h1[(size_t)N_NODES * D_HID];
__device__ __nv_bfloat16 g_agg[(size_t)N_NODES * D_HID];  // bf16 (fp32-accumulated)
__device__ float g_pool[N_GRAPHS * D_HID];
__device__ int   g_cnt[N_GRAPHS];
__device__ int   g_is32_ei;
__device__ int   g_is32_batch;

__device__ __forceinline__ float selu_f(float v) {
    const float a = 1.6732632423543772f, s = 1.0507009873554805f;
    return v > 0.f ? s * v : s * a * (expf(v) - 1.f);
}

__device__ __forceinline__ int load_idx(const void* p, long long i, int is32) {
    if (is32) return ((const int*)p)[i];
    return (int)((const long long*)p)[i];
}

__device__ __forceinline__ unsigned f2tf32(float f) {
    unsigned r;
    asm("cvt.rna.tf32.f32 %0, %1;" : "=r"(r) : "f"(f));
    return r;
}

// ---------------- init + dtype sniff (merged) --------------------------------
__global__ void init_kernel(const int* __restrict__ ei32, const int* __restrict__ b32) {
    int i = blockIdx.x * blockDim.x + threadIdx.x;
    if (i < N_NODES) g_deg[i] = 0;
    if (i < N_GRAPHS * D_HID) g_pool[i] = 0.f;
    if (i < N_GRAPHS) g_cnt[i] = 0;
    if (i < N_SCANBLK) g_scanstate[i] = 0ULL;
    if (i == 0) g_ticket = 0;
    if (blockIdx.x == 0) {
        int v = 0, w = 0;
        #pragma unroll
        for (int j = 0; j < 16; j++) {
            int idx = threadIdx.x + j * 256;
            v |= ei32[2 * idx + 1];
            w |= b32[2 * idx + 1];
        }
        __shared__ int s_ei, s_b;
        if (threadIdx.x == 0) { s_ei = 0; s_b = 0; }
        __syncthreads();
        if (v) s_ei = 1;
        if (w) s_b = 1;
        __syncthreads();
        if (threadIdx.x == 0) { g_is32_ei = s_ei; g_is32_batch = s_b; }
    }
}

// 4 edges per thread: 4 independent atomics in flight
__global__ void deg_count_kernel(const void* __restrict__ ei, const void* __restrict__ batch) {
    int i = blockIdx.x * blockDim.x + threadIdx.x;
    int is32 = g_is32_ei;
    int e = i * 4;
    if (e + 3 < N_EDGES) {
        int d0 = load_idx(ei, (long long)N_EDGES + e + 0, is32);
        int d1 = load_idx(ei, (long long)N_EDGES + e + 1, is32);
        int d2 = load_idx(ei, (long long)N_EDGES + e + 2, is32);
        int d3 = load_idx(ei, (long long)N_EDGES + e + 3, is32);
        atomicAdd(&g_deg[d0], 1);
        atomicAdd(&g_deg[d1], 1);
        atomicAdd(&g_deg[d2], 1);
        atomicAdd(&g_deg[d3], 1);
    } else {
        for (int u = e; u < N_EDGES; u++)
            atomicAdd(&g_deg[load_idx(ei, (long long)N_EDGES + u, is32)], 1);
    }
    if (i < N_NODES) atomicAdd(&g_cnt[load_idx(batch, i, g_is32_batch)], 1);
}

// ------- single-kernel decoupled-lookback scan (+cursor+dinv init) -----------
__global__ void __launch_bounds__(SCAN_B) scan_one() {
    __shared__ int warp_sums[32];
    __shared__ int s_bid, s_exc;
    int t = threadIdx.x;
    if (t == 0) s_bid = atomicAdd(&g_ticket, 1);
    __syncthreads();
    int b = s_bid;
    int i = b * SCAN_B + t;
    int v = (i < N_NODES) ? g_deg[i] : 0;
    int x = v;
    #pragma unroll
    for (int off = 1; off < 32; off <<= 1) {
        int y = __shfl_up_sync(0xffffffffu, x, off);
        if ((t & 31) >= off) x += y;
    }
    if ((t & 31) == 31) warp_sums[t >> 5] = x;
    __syncthreads();
    if (t < 32) {
        int s = warp_sums[t];
        #pragma unroll
        for (int off = 1; off < 32; off <<= 1) {
            int y = __shfl_up_sync(0xffffffffu, s, off);
            if (t >= off) s += y;
        }
        warp_sums[t] = s;
    }
    __syncthreads();
    int inc = x + ((t >= 32) ? warp_sums[(t >> 5) - 1] : 0);

    if (t == 0) {
        int total = warp_sums[31];
        if (b == 0) {
            atomicExch(&g_scanstate[0], (2ULL << 32) | (unsigned)total);
            s_exc = 0;
        } else {
            atomicExch(&g_scanstate[b], (1ULL << 32) | (unsigned)total);
            int exc = 0;
            int j = b - 1;
            while (true) {
                unsigned long long st;
                do { st = atomicAdd(&g_scanstate[j], 0ULL); } while ((st >> 32) == 0ULL);
                exc += (int)(unsigned)st;
                if ((st >> 32) == 2ULL) break;
                j--;
            }
            atomicExch(&g_scanstate[b], (2ULL << 32) | (unsigned)(total + exc));
            s_exc = exc;
        }
    }
    __syncthreads();
    int exc = s_exc;
    int r = exc + inc - v;   // exclusive prefix
    if (i < N_NODES) {
        g_rowptr[i] = r;
        g_cursor[i] = r;
        g_dinv[i] = rsqrtf((float)(v + 1));
    }
    if (i == N_NODES - 1) g_rowptr[N_NODES] = exc + inc;
}

// 4 edges per thread: 4 independent cursor atomics in flight
__global__ void fill_kernel(const void* __restrict__ ei) {
    int i = blockIdx.x * blockDim.x + threadIdx.x;
    int is32 = g_is32_ei;
    int e = i * 4;
    if (e + 3 < N_EDGES) {
        int d0 = load_idx(ei, (long long)N_EDGES + e + 0, is32);
        int d1 = load_idx(ei, (long long)N_EDGES + e + 1, is32);
        int d2 = load_idx(ei, (long long)N_EDGES + e + 2, is32);
        int d3 = load_idx(ei, (long long)N_EDGES + e + 3, is32);
        int s0 = load_idx(ei, e + 0, is32);
        int s1 = load_idx(ei, e + 1, is32);
        int s2 = load_idx(ei, e + 2, is32);
        int s3 = load_idx(ei, e + 3, is32);
        int p0 = atomicAdd(&g_cursor[d0], 1);
        int p1 = atomicAdd(&g_cursor[d1], 1);
        int p2 = atomicAdd(&g_cursor[d2], 1);
        int p3 = atomicAdd(&g_cursor[d3], 1);
        g_colidx[p0] = s0;
        g_colidx[p1] = s1;
        g_colidx[p2] = s2;
        g_colidx[p3] = s3;
    } else {
        for (int u = e; u < N_EDGES; u++) {
            int d = load_idx(ei, (long long)N_EDGES + u, is32);
            int p = atomicAdd(&g_cursor[d], 1);
            g_colidx[p] = load_idx(ei, u, is32);
        }
    }
}

// ------- layer 1 fused: aggregate x into smem (unroll-2), then GEMM ----------
__global__ void gemm1_fused(const float* __restrict__ x,
                            const float* __restrict__ W1, const float* __restrict__ b1) {
    __shared__ __align__(16) float sx[32][16];
    int row0 = blockIdx.x * 32;
    int tid = threadIdx.x;  // 256
    int warp = tid >> 5, lane = tid & 31;
    int f = lane & 15;
    #pragma unroll
    for (int pair = 0; pair < 2; pair++) {
        int r = warp * 4 + pair * 2 + (lane >> 4);
        int row = row0 + r;
        float out = 0.f;
        if (row < N_NODES) {
            float di = g_dinv[row];
            float acc = 0.f;
            if (f < 14) acc = di * x[(size_t)row * 14 + f];
            int e0 = g_rowptr[row], e1 = g_rowptr[row + 1];
            int e = e0;
            for (; e + 2 <= e1; e += 2) {
                int s0 = g_colidx[e], s1 = g_colidx[e + 1];
                float ds0 = g_dinv[s0], ds1 = g_dinv[s1];
                float v0 = 0.f, v1 = 0.f;
                if (f < 14) {
                    v0 = x[(size_t)s0 * 14 + f];
                    v1 = x[(size_t)s1 * 14 + f];
                }
                acc += ds0 * v0 + ds1 * v1;
            }
            if (e < e1) {
                int s = g_colidx[e];
                float ds = g_dinv[s];
                if (f < 14) acc += ds * x[(size_t)s * 14 + f];
            }
            out = (f < 14) ? di * acc : 0.f;
        }
        sx[r][f] = out;
    }
    __syncthreads();
    float w[14];
    #pragma unroll
    for (int k = 0; k < 14; k++) w[k] = W1[k * 256 + tid];
    float bj = b1[tid];
    for (int r = 0; r < 32; r++) {
        int row = row0 + r;
        if (row >= N_NODES) break;
        float acc = bj;
        #pragma unroll
        for (int k = 0; k < 14; k++) acc += sx[r][k] * w[k];
        g_h1[(size_t)row * 256 + tid] = __float2bfloat16(selu_f(acc));
    }
}

// ------- layer 2 aggregate: bf16 gather, unroll 8/4/1 ladder (MLP=8) ---------
__global__ void agg2_kernel() {
    int w = (blockIdx.x * blockDim.x + threadIdx.x) >> 5;
    int lane = threadIdx.x & 31;
    if (w >= N_NODES) return;
    float di = g_dinv[w];
    float acc[8];
    {
        float4 raw = ((const float4*)(g_h1 + (size_t)w * 256))[lane];
        const __nv_bfloat162* p = (const __nv_bfloat162*)&raw;
        #pragma unroll
        for (int q = 0; q < 4; q++) {
            float2 v = __bfloat1622float2(p[q]);
            acc[2 * q]     = di * v.x;
            acc[2 * q + 1] = di * v.y;
        }
    }
    int e0 = g_rowptr[w], e1 = g_rowptr[w + 1];
    int e = e0;
    for (; e + 8 <= e1; e += 8) {
        int s[8];
        float ds[8];
        float4 raw[8];
        #pragma unroll
        for (int u = 0; u < 8; u++) s[u] = g_colidx[e + u];
        #pragma unroll
        for (int u = 0; u < 8; u++) ds[u] = g_dinv[s[u]];
        #pragma unroll
        for (int u = 0; u < 8; u++)
            raw[u] = ((const float4*)(g_h1 + (size_t)s[u] * 256))[lane];
        #pragma unroll
        for (int u = 0; u < 8; u++) {
            const __nv_bfloat162* p = (const __nv_bfloat162*)&raw[u];
            #pragma unroll
            for (int q = 0; q < 4; q++) {
                float2 v = __bfloat1622float2(p[q]);
                acc[2 * q]     += ds[u] * v.x;
                acc[2 * q + 1] += ds[u] * v.y;
            }
        }
    }
    for (; e + 4 <= e1; e += 4) {
        int s[4];
        float ds[4];
        float4 raw[4];
        #pragma unroll
        for (int u = 0; u < 4; u++) s[u] = g_colidx[e + u];
        #pragma unroll
        for (int u = 0; u < 4; u++) ds[u] = g_dinv[s[u]];
        #pragma unroll
        for (int u = 0; u < 4; u++)
            raw[u] = ((const float4*)(g_h1 + (size_t)s[u] * 256))[lane];
        #pragma unroll
        for (int u = 0; u < 4; u++) {
            const __nv_bfloat162* p = (const __nv_bfloat162*)&raw[u];
            #pragma unroll
            for (int q = 0; q < 4; q++) {
                float2 v = __bfloat1622float2(p[q]);
                acc[2 * q]     += ds[u] * v.x;
                acc[2 * q + 1] += ds[u] * v.y;
            }
        }
    }
    for (; e < e1; e++) {
        int s = g_colidx[e];
        float ds = g_dinv[s];
        float4 raw = ((const float4*)(g_h1 + (size_t)s * 256))[lane];
        const __nv_bfloat162* p = (const __nv_bfloat162*)&raw;
        #pragma unroll
        for (int q = 0; q < 4; q++) {
            float2 v = __bfloat1622float2(p[q]);
            acc[2 * q]     += ds * v.x;
            acc[2 * q + 1] += ds * v.y;
        }
    }
    __nv_bfloat162 h[4];
    #pragma unroll
    for (int q = 0; q < 4; q++)
        h[q] = __floats2bfloat162_rn(di * acc[2 * q], di * acc[2 * q + 1]);
    ((float4*)(g_agg + (size_t)w * 256))[lane] = *(float4*)h;
}

// ---------------- GEMM2 (tf32 TC, bf16 A) with fused bias+selu+pool ----------
#define GM 128
#define GN 128
#define GK 32
#define GS (GM + 4)

__global__ void __launch_bounds__(256, 2) gemm2_tc(const float* __restrict__ W,
                                                   const float* __restrict__ bias,
                                                   const void* __restrict__ batch) {
    __shared__ unsigned As[GK][GS];
    __shared__ unsigned Bs[GK][GS];
    int m0 = blockIdx.x * GM, n0 = blockIdx.y * GN;
    int tid = threadIdx.x;
    int lane = tid & 31, warp = tid >> 5;
    int wm = (warp >> 1) * 32;
    int wn = (warp & 1) * 64;
    int g = lane >> 2, tg = lane & 3;

    float d[2][8][4];
    #pragma unroll
    for (int mi = 0; mi < 2; mi++)
        #pragma unroll
        for (int ni = 0; ni < 8; ni++)
            #pragma unroll
            for (int q = 0; q < 4; q++) d[mi][ni][q] = 0.f;

    for (int k0 = 0; k0 < 256; k0 += GK) {
        #pragma unroll
        for (int it = 0; it < 2; it++) {
            int idx = tid + it * 256;        // 0..511
            int row = idx >> 2;              // 0..127
            int c = (idx & 3) * 8;           // 0,8,16,24
            float4 raw = make_float4(0.f, 0.f, 0.f, 0.f);
            if (m0 + row < N_NODES)
                raw = *(const float4*)(g_agg + (size_t)(m0 + row) * 256 + k0 + c);
            const __nv_bfloat162* p = (const __nv_bfloat162*)&raw;
            #pragma unroll
            for (int q = 0; q < 4; q++) {
                float2 v = __bfloat1622float2(p[q]);
                As[c + 2 * q][row]     = f2tf32(v.x);
                As[c + 2 * q + 1][row] = f2tf32(v.y);
            }
        }
        #pragma unroll
        for (int it = 0; it < 4; it++) {
            int idx = tid + it * 256;
            int kr = idx >> 5;
            int nc = (idx & 31) * 4;
            float4 bv = *(const float4*)(W + (size_t)(k0 + kr) * 256 + n0 + nc);
            Bs[kr][nc + 0] = f2tf32(bv.x);
            Bs[kr][nc + 1] = f2tf32(bv.y);
            Bs[kr][nc + 2] = f2tf32(bv.z);
            Bs[kr][nc + 3] = f2tf32(bv.w);
        }
        __syncthreads();

        #pragma unroll
        for (int kk = 0; kk < GK; kk += 8) {
            unsigned a[2][4], b[8][2];
            #pragma unroll
            for (int mi = 0; mi < 2; mi++) {
                int mb = wm + mi * 16;
                a[mi][0] = As[kk + tg][mb + g];
                a[mi][1] = As[kk + tg][mb + g + 8];
                a[mi][2] = As[kk + tg + 4][mb + g];
                a[mi][3] = As[kk + tg + 4][mb + g + 8];
            }
            #pragma unroll
            for (int ni = 0; ni < 8; ni++) {
                int nb = wn + ni * 8;
                b[ni][0] = Bs[kk + tg][nb + g];
                b[ni][1] = Bs[kk + tg + 4][nb + g];
            }
            #pragma unroll
            for (int mi = 0; mi < 2; mi++)
                #pragma unroll
                for (int ni = 0; ni < 8; ni++)
                    asm volatile(
                        "mma.sync.aligned.m16n8k8.row.col.f32.tf32.tf32.f32 "
                        "{%0,%1,%2,%3},{%4,%5,%6,%7},{%8,%9},{%0,%1,%2,%3};"
                        : "+f"(d[mi][ni][0]), "+f"(d[mi][ni][1]),
                          "+f"(d[mi][ni][2]), "+f"(d[mi][ni][3])
                        : "r"(a[mi][0]), "r"(a[mi][1]), "r"(a[mi][2]), "r"(a[mi][3]),
                          "r"(b[ni][0]), "r"(b[ni][1]));
        }
        __syncthreads();
    }

    // ---- fused epilogue: bias + selu + segmented pool -> g_pool atomics ----
    int is32 = g_is32_batch;
    #pragma unroll
    for (int mi = 0; mi < 2; mi++) {
        int rbase = m0 + wm + mi * 16;
        int r0 = rbase + g;
        int r1 = r0 + 8;
        bool full = (rbase + 15) < N_NODES;
        int gid_first = load_idx(batch, full ? rbase : (N_NODES - 1), is32);
        int gid_last  = load_idx(batch, full ? (rbase + 15) : (N_NODES - 1), is32);
        bool uniform = full && (gid_first == gid_last);
        #pragma unroll
        for (int ni = 0; ni < 8; ni++) {
            int c0 = n0 + wn + ni * 8 + 2 * tg;
            float bz0 = bias[c0], bz1 = bias[c0 + 1];
            float v00 = selu_f(d[mi][ni][0] + bz0);
            float v01 = selu_f(d[mi][ni][1] + bz1);
            float v10 = selu_f(d[mi][ni][2] + bz0);
            float v11 = selu_f(d[mi][ni][3] + bz1);
            if (uniform) {
                float s0 = v00 + v10;
                float s1 = v01 + v11;
                #pragma unroll
                for (int off = 4; off < 32; off <<= 1) {
                    s0 += __shfl_xor_sync(0xffffffffu, s0, off);
                    s1 += __shfl_xor_sync(0xffffffffu, s1, off);
                }
                if (g == 0) {
                    atomicAdd(&g_pool[gid_first * 256 + c0], s0);
                    atomicAdd(&g_pool[gid_first * 256 + c0 + 1], s1);
                }
            } else {
                if (r0 < N_NODES) {
                    int gr = load_idx(batch, r0, is32);
                    atomicAdd(&g_pool[gr * 256 + c0], v00);
                    atomicAdd(&g_pool[gr * 256 + c0 + 1], v01);
                }
                if (r1 < N_NODES) {
                    int gr = load_idx(batch, r1, is32);
                    atomicAdd(&g_pool[gr * 256 + c0], v10);
                    atomicAdd(&g_pool[gr * 256 + c0 + 1], v11);
                }
            }
        }
    }
}

// ---------------- head -------------------------------------------------------
__global__ void head_kernel(const float* __restrict__ fc1w, const float* __restrict__ fc1b,
                            const float* __restrict__ fc2w, const float* __restrict__ fc2b,
                            float* __restrict__ out) {
    __shared__ __align__(16) float sp[256];
    __shared__ __align__(16) float sg[128];
    __shared__ float slog[2];
    int g = blockIdx.x, t = threadIdx.x;  // 128 threads
    float c = fmaxf((float)g_cnt[g], 1.0f);
    for (int j = t; j < 256; j += 128) sp[j] = selu_f(g_pool[g * 256 + j] / c);
    __syncthreads();
    float acc = fc1b[t];
    for (int k = 0; k < 256; k++) acc += sp[k] * fc1w[k * 128 + t];
    sg[t] = selu_f(acc);
    __syncthreads();
    if (t < 2) {
        float a = fc2b[t];
        for (int k = 0; k < 128; k++) a += sg[k] * fc2w[k * 2 + t];
        slog[t] = a;
    }
    __syncthreads();
    if (t < 2) {
        float m = fmaxf(slog[0], slog[1]);
        float lse = m + logf(expf(slog[0] - m) + expf(slog[1] - m));
        out[g * 2 + t] = slog[t] - lse;
    }
}

// ---------------- launch -----------------------------------------------------
extern "C" void kernel_launch(void* const* d_in, const int* in_sizes, int n_in,
                              void* d_out, int out_size) {
    const float* x     = (const float*)d_in[0];
    const void*  ei    = d_in[1];
    const void*  batch = d_in[2];
    const float* W1  = (const float*)d_in[3];
    const float* b1  = (const float*)d_in[4];
    const float* W2  = (const float*)d_in[5];
    const float* b2  = (const float*)d_in[6];
    const float* f1w = (const float*)d_in[7];
    const float* f1b = (const float*)d_in[8];
    const float* f2w = (const float*)d_in[9];
    const float* f2b = (const float*)d_in[10];
    float* out = (float*)d_out;

    init_kernel<<<256, 256>>>((const int*)ei, (const int*)batch);
    deg_count_kernel<<<(N_EDGES / 4 + 255) / 256, 256>>>(ei, batch);
    scan_one<<<N_SCANBLK, SCAN_B>>>();
    fill_kernel<<<(N_EDGES / 4 + 255) / 256, 256>>>(ei);

    gemm1_fused<<<(N_NODES + 31) / 32, 256>>>(x, W1, b1);

    agg2_kernel<<<(N_NODES * 32 + 255) / 256, 256>>>();
    {
        dim3 grid((N_NODES + GM - 1) / GM, 256 / GN);
        gemm2_tc<<<grid, 256>>>(W2, b2, batch);
    }

    head_kernel<<<N_GRAPHS, 128>>>(f1w, f1b, f2w, f2b, out);
}

// round 13
// speedup vs baseline: 2.2304x; 1.0189x over previous
#include <cuda_runtime.h>
#include <cuda_bf16.h>
#include <math.h>

#define N_NODES 50000
#define N_EDGES 800000
#define N_GRAPHS 256
#define D_HID 256
#define SCAN_B 1024
#define N_SCANBLK ((N_NODES + SCAN_B - 1) / SCAN_B)   // 49

// ---------------- scratch (device globals; all self-restoring) ---------------
__device__ float g_dinv[N_NODES];
__device__ int   g_deg[N_NODES];                       // restored by scan_one
__device__ int   g_rowptr[N_NODES + 1];
__device__ int   g_cursor[N_NODES];
__device__ int   g_colidx[N_EDGES];
__device__ unsigned long long g_scanstate[N_SCANBLK];  // restored by fill
__device__ int   g_ticket;                             // restored by fill
__device__ __nv_bfloat16 g_h1[(size_t)N_NODES * D_HID];
__device__ __nv_bfloat16 g_agg[(size_t)N_NODES * D_HID];
__device__ float g_pool[N_GRAPHS * D_HID];             // restored by head
__device__ int   g_cnt[N_GRAPHS];                      // restored by head
__device__ int   g_is32_ei;
__device__ int   g_is32_batch;

__device__ __forceinline__ float selu_f(float v) {
    const float a = 1.6732632423543772f, s = 1.0507009873554805f;
    return v > 0.f ? s * v : s * a * (expf(v) - 1.f);
}

__device__ __forceinline__ int load_idx(const void* p, long long i, int is32) {
    if (is32) return ((const int*)p)[i];
    return (int)((const long long*)p)[i];
}

__device__ __forceinline__ unsigned f2tf32(float f) {
    unsigned r;
    asm("cvt.rna.tf32.f32 %0, %1;" : "=r"(r) : "f"(f));
    return r;
}

// ------ deg/cnt histograms with per-block dtype sniff (no init kernel) -------
__global__ void deg_count_kernel(const void* __restrict__ ei, const void* __restrict__ batch) {
    __shared__ int s_ei, s_b;
    int t = threadIdx.x;
    if (t < 32) {
        // odd int32 words, strided 512 words apart: int64 data -> all zero
        int v = ((const int*)ei)[2 * (t * 256) + 1];
        unsigned m = __ballot_sync(0xffffffffu, v != 0);
        int w = ((const int*)batch)[2 * (t * 256) + 1];
        unsigned m2 = __ballot_sync(0xffffffffu, w != 0);
        if (t == 0) { s_ei = (m != 0); s_b = (m2 != 0); }
    }
    __syncthreads();
    int is32e = s_ei, is32b = s_b;
    int i = blockIdx.x * blockDim.x + t;
    if (i == 0) { g_is32_ei = is32e; g_is32_batch = is32b; }
    if (i < N_EDGES) atomicAdd(&g_deg[load_idx(ei, (long long)N_EDGES + i, is32e)], 1);
    if (i < N_NODES) atomicAdd(&g_cnt[load_idx(batch, i, is32b)], 1);
}

// ------- single-kernel decoupled-lookback scan (+cursor+dinv, deg restore) ---
__global__ void __launch_bounds__(SCAN_B) scan_one() {
    __shared__ int warp_sums[32];
    __shared__ int s_bid, s_exc;
    int t = threadIdx.x;
    if (t == 0) s_bid = atomicAdd(&g_ticket, 1);
    __syncthreads();
    int b = s_bid;
    int i = b * SCAN_B + t;
    int v = (i < N_NODES) ? g_deg[i] : 0;
    int x = v;
    #pragma unroll
    for (int off = 1; off < 32; off <<= 1) {
        int y = __shfl_up_sync(0xffffffffu, x, off);
        if ((t & 31) >= off) x += y;
    }
    if ((t & 31) == 31) warp_sums[t >> 5] = x;
    __syncthreads();
    if (t < 32) {
        int s = warp_sums[t];
        #pragma unroll
        for (int off = 1; off < 32; off <<= 1) {
            int y = __shfl_up_sync(0xffffffffu, s, off);
            if (t >= off) s += y;
        }
        warp_sums[t] = s;
    }
    __syncthreads();
    int inc = x + ((t >= 32) ? warp_sums[(t >> 5) - 1] : 0);

    if (t == 0) {
        int total = warp_sums[31];
        if (b == 0) {
            atomicExch(&g_scanstate[0], (2ULL << 32) | (unsigned)total);
            s_exc = 0;
        } else {
            atomicExch(&g_scanstate[b], (1ULL << 32) | (unsigned)total);
            int exc = 0;
            int j = b - 1;
            while (true) {
                unsigned long long st;
                do { st = atomicAdd(&g_scanstate[j], 0ULL); } while ((st >> 32) == 0ULL);
                exc += (int)(unsigned)st;
                if ((st >> 32) == 2ULL) break;
                j--;
            }
            atomicExch(&g_scanstate[b], (2ULL << 32) | (unsigned)(total + exc));
            s_exc = exc;
        }
    }
    __syncthreads();
    int exc = s_exc;
    int r = exc + inc - v;   // exclusive prefix
    if (i < N_NODES) {
        g_rowptr[i] = r;
        g_cursor[i] = r;
        g_dinv[i] = rsqrtf((float)(v + 1));
        g_deg[i] = 0;                       // restore for next run
    }
    if (i == N_NODES - 1) g_rowptr[N_NODES] = exc + inc;
}

// fill colidx (1 edge/thread: TLP-bound, per R10 measurement) + scan-state reset
__global__ void fill_kernel(const void* __restrict__ ei) {
    int i = blockIdx.x * blockDim.x + threadIdx.x;
    int is32 = g_is32_ei;
    if (i < N_EDGES) {
        int d = load_idx(ei, (long long)N_EDGES + i, is32);
        int p = atomicAdd(&g_cursor[d], 1);
        g_colidx[p] = load_idx(ei, i, is32);
    }
    if (i < N_SCANBLK) g_scanstate[i] = 0ULL;   // restore (scan_one fully done)
    if (i == N_SCANBLK) g_ticket = 0;           // restore
}

// ------- layer 1 fused: aggregate x into smem (unroll-2), then GEMM ----------
__global__ void gemm1_fused(const float* __restrict__ x,
                            const float* __restrict__ W1, const float* __restrict__ b1) {
    __shared__ __align__(16) float sx[32][16];
    int row0 = blockIdx.x * 32;
    int tid = threadIdx.x;  // 256
    int warp = tid >> 5, lane = tid & 31;
    int f = lane & 15;
    #pragma unroll
    for (int pair = 0; pair < 2; pair++) {
        int r = warp * 4 + pair * 2 + (lane >> 4);
        int row = row0 + r;
        float out = 0.f;
        if (row < N_NODES) {
            float di = g_dinv[row];
            float acc = 0.f;
            if (f < 14) acc = di * x[(size_t)row * 14 + f];
            int e0 = g_rowptr[row], e1 = g_rowptr[row + 1];
            int e = e0;
            for (; e + 2 <= e1; e += 2) {
                int s0 = g_colidx[e], s1 = g_colidx[e + 1];
                float ds0 = g_dinv[s0], ds1 = g_dinv[s1];
                float v0 = 0.f, v1 = 0.f;
                if (f < 14) {
                    v0 = x[(size_t)s0 * 14 + f];
                    v1 = x[(size_t)s1 * 14 + f];
                }
                acc += ds0 * v0 + ds1 * v1;
            }
            if (e < e1) {
                int s = g_colidx[e];
                float ds = g_dinv[s];
                if (f < 14) acc += ds * x[(size_t)s * 14 + f];
            }
            out = (f < 14) ? di * acc : 0.f;
        }
        sx[r][f] = out;
    }
    __syncthreads();
    float w[14];
    #pragma unroll
    for (int k = 0; k < 14; k++) w[k] = W1[k * 256 + tid];
    float bj = b1[tid];
    for (int r = 0; r < 32; r++) {
        int row = row0 + r;
        if (row >= N_NODES) break;
        float acc = bj;
        #pragma unroll
        for (int k = 0; k < 14; k++) acc += sx[r][k] * w[k];
        g_h1[(size_t)row * 256 + tid] = __float2bfloat16(selu_f(acc));
    }
}

// ------- layer 2 aggregate: bf16 gather, unroll 8/4/1 ladder -----------------
__global__ void agg2_kernel() {
    int w = (blockIdx.x * blockDim.x + threadIdx.x) >> 5;
    int lane = threadIdx.x & 31;
    if (w >= N_NODES) return;
    float di = g_dinv[w];
    float acc[8];
    {
        float4 raw = ((const float4*)(g_h1 + (size_t)w * 256))[lane];
        const __nv_bfloat162* p = (const __nv_bfloat162*)&raw;
        #pragma unroll
        for (int q = 0; q < 4; q++) {
            float2 v = __bfloat1622float2(p[q]);
            acc[2 * q]     = di * v.x;
            acc[2 * q + 1] = di * v.y;
        }
    }
    int e0 = g_rowptr[w], e1 = g_rowptr[w + 1];
    int e = e0;
    for (; e + 8 <= e1; e += 8) {
        int s[8];
        float ds[8];
        float4 raw[8];
        #pragma unroll
        for (int u = 0; u < 8; u++) s[u] = g_colidx[e + u];
        #pragma unroll
        for (int u = 0; u < 8; u++) ds[u] = g_dinv[s[u]];
        #pragma unroll
        for (int u = 0; u < 8; u++)
            raw[u] = ((const float4*)(g_h1 + (size_t)s[u] * 256))[lane];
        #pragma unroll
        for (int u = 0; u < 8; u++) {
            const __nv_bfloat162* p = (const __nv_bfloat162*)&raw[u];
            #pragma unroll
            for (int q = 0; q < 4; q++) {
                float2 v = __bfloat1622float2(p[q]);
                acc[2 * q]     += ds[u] * v.x;
                acc[2 * q + 1] += ds[u] * v.y;
            }
        }
    }
    for (; e + 4 <= e1; e += 4) {
        int s[4];
        float ds[4];
        float4 raw[4];
        #pragma unroll
        for (int u = 0; u < 4; u++) s[u] = g_colidx[e + u];
        #pragma unroll
        for (int u = 0; u < 4; u++) ds[u] = g_dinv[s[u]];
        #pragma unroll
        for (int u = 0; u < 4; u++)
            raw[u] = ((const float4*)(g_h1 + (size_t)s[u] * 256))[lane];
        #pragma unroll
        for (int u = 0; u < 4; u++) {
            const __nv_bfloat162* p = (const __nv_bfloat162*)&raw[u];
            #pragma unroll
            for (int q = 0; q < 4; q++) {
                float2 v = __bfloat1622float2(p[q]);
                acc[2 * q]     += ds[u] * v.x;
                acc[2 * q + 1] += ds[u] * v.y;
            }
        }
    }
    for (; e < e1; e++) {
        int s = g_colidx[e];
        float ds = g_dinv[s];
        float4 raw = ((const float4*)(g_h1 + (size_t)s * 256))[lane];
        const __nv_bfloat162* p = (const __nv_bfloat162*)&raw;
        #pragma unroll
        for (int q = 0; q < 4; q++) {
            float2 v = __bfloat1622float2(p[q]);
            acc[2 * q]     += ds * v.x;
            acc[2 * q + 1] += ds * v.y;
        }
    }
    __nv_bfloat162 h[4];
    #pragma unroll
    for (int q = 0; q < 4; q++)
        h[q] = __floats2bfloat162_rn(di * acc[2 * q], di * acc[2 * q + 1]);
    ((float4*)(g_agg + (size_t)w * 256))[lane] = *(float4*)h;
}

// ---------------- GEMM2 (tf32 TC, bf16 A) with fused bias+selu+pool ----------
#define GM 128
#define GN 128
#define GK 32
#define GS (GM + 4)

__global__ void __launch_bounds__(256, 2) gemm2_tc(const float* __restrict__ W,
                                                   const float* __restrict__ bias,
                                                   const void* __restrict__ batch) {
    __shared__ unsigned As[GK][GS];
    __shared__ unsigned Bs[GK][GS];
    int m0 = blockIdx.x * GM, n0 = blockIdx.y * GN;
    int tid = threadIdx.x;
    int lane = tid & 31, warp = tid >> 5;
    int wm = (warp >> 1) * 32;
    int wn = (warp & 1) * 64;
    int g = lane >> 2, tg = lane & 3;

    float d[2][8][4];
    #pragma unroll
    for (int mi = 0; mi < 2; mi++)
        #pragma unroll
        for (int ni = 0; ni < 8; ni++)
            #pragma unroll
            for (int q = 0; q < 4; q++) d[mi][ni][q] = 0.f;

    for (int k0 = 0; k0 < 256; k0 += GK) {
        #pragma unroll
        for (int it = 0; it < 2; it++) {
            int idx = tid + it * 256;
            int row = idx >> 2;
            int c = (idx & 3) * 8;
            float4 raw = make_float4(0.f, 0.f, 0.f, 0.f);
            if (m0 + row < N_NODES)
                raw = *(const float4*)(g_agg + (size_t)(m0 + row) * 256 + k0 + c);
            const __nv_bfloat162* p = (const __nv_bfloat162*)&raw;
            #pragma unroll
            for (int q = 0; q < 4; q++) {
                float2 v = __bfloat1622float2(p[q]);
                As[c + 2 * q][row]     = f2tf32(v.x);
                As[c + 2 * q + 1][row] = f2tf32(v.y);
            }
        }
        #pragma unroll
        for (int it = 0; it < 4; it++) {
            int idx = tid + it * 256;
            int kr = idx >> 5;
            int nc = (idx & 31) * 4;
            float4 bv = *(const float4*)(W + (size_t)(k0 + kr) * 256 + n0 + nc);
            Bs[kr][nc + 0] = f2tf32(bv.x);
            Bs[kr][nc + 1] = f2tf32(bv.y);
            Bs[kr][nc + 2] = f2tf32(bv.z);
            Bs[kr][nc + 3] = f2tf32(bv.w);
        }
        __syncthreads();

        #pragma unroll
        for (int kk = 0; kk < GK; kk += 8) {
            unsigned a[2][4], b[8][2];
            #pragma unroll
            for (int mi = 0; mi < 2; mi++) {
                int mb = wm + mi * 16;
                a[mi][0] = As[kk + tg][mb + g];
                a[mi][1] = As[kk + tg][mb + g + 8];
                a[mi][2] = As[kk + tg + 4][mb + g];
                a[mi][3] = As[kk + tg + 4][mb + g + 8];
            }
            #pragma unroll
            for (int ni = 0; ni < 8; ni++) {
                int nb = wn + ni * 8;
                b[ni][0] = Bs[kk + tg][nb + g];
                b[ni][1] = Bs[kk + tg + 4][nb + g];
            }
            #pragma unroll
            for (int mi = 0; mi < 2; mi++)
                #pragma unroll
                for (int ni = 0; ni < 8; ni++)
                    asm volatile(
                        "mma.sync.aligned.m16n8k8.row.col.f32.tf32.tf32.f32 "
                        "{%0,%1,%2,%3},{%4,%5,%6,%7},{%8,%9},{%0,%1,%2,%3};"
                        : "+f"(d[mi][ni][0]), "+f"(d[mi][ni][1]),
                          "+f"(d[mi][ni][2]), "+f"(d[mi][ni][3])
                        : "r"(a[mi][0]), "r"(a[mi][1]), "r"(a[mi][2]), "r"(a[mi][3]),
                          "r"(b[ni][0]), "r"(b[ni][1]));
        }
        __syncthreads();
    }

    // ---- fused epilogue: bias + selu + segmented pool -> g_pool atomics ----
    int is32 = g_is32_batch;
    #pragma unroll
    for (int mi = 0; mi < 2; mi++) {
        int rbase = m0 + wm + mi * 16;
        int r0 = rbase + g;
        int r1 = r0 + 8;
        bool full = (rbase + 15) < N_NODES;
        int gid_first = load_idx(batch, full ? rbase : (N_NODES - 1), is32);
        int gid_last  = load_idx(batch, full ? (rbase + 15) : (N_NODES - 1), is32);
        bool uniform = full && (gid_first == gid_last);
        #pragma unroll
        for (int ni = 0; ni < 8; ni++) {
            int c0 = n0 + wn + ni * 8 + 2 * tg;
            float bz0 = bias[c0], bz1 = bias[c0 + 1];
            float v00 = selu_f(d[mi][ni][0] + bz0);
            float v01 = selu_f(d[mi][ni][1] + bz1);
            float v10 = selu_f(d[mi][ni][2] + bz0);
            float v11 = selu_f(d[mi][ni][3] + bz1);
            if (uniform) {
                float s0 = v00 + v10;
                float s1 = v01 + v11;
                #pragma unroll
                for (int off = 4; off < 32; off <<= 1) {
                    s0 += __shfl_xor_sync(0xffffffffu, s0, off);
                    s1 += __shfl_xor_sync(0xffffffffu, s1, off);
                }
                if (g == 0) {
                    atomicAdd(&g_pool[gid_first * 256 + c0], s0);
                    atomicAdd(&g_pool[gid_first * 256 + c0 + 1], s1);
                }
            } else {
                if (r0 < N_NODES) {
                    int gr = load_idx(batch, r0, is32);
                    atomicAdd(&g_pool[gr * 256 + c0], v00);
                    atomicAdd(&g_pool[gr * 256 + c0 + 1], v01);
                }
                if (r1 < N_NODES) {
                    int gr = load_idx(batch, r1, is32);
                    atomicAdd(&g_pool[gr * 256 + c0], v10);
                    atomicAdd(&g_pool[gr * 256 + c0 + 1], v11);
                }
            }
        }
    }
}

// ---------------- head (restores g_pool/g_cnt to zero) -----------------------
__global__ void head_kernel(const float* __restrict__ fc1w, const float* __restrict__ fc1b,
                            const float* __restrict__ fc2w, const float* __restrict__ fc2b,
                            float* __restrict__ out) {
    __shared__ __align__(16) float sp[256];
    __shared__ __align__(16) float sg[128];
    __shared__ float slog[2];
    int g = blockIdx.x, t = threadIdx.x;  // 128 threads
    float c = fmaxf((float)g_cnt[g], 1.0f);
    for (int j = t; j < 256; j += 128) {
        sp[j] = selu_f(g_pool[g * 256 + j] / c);
        g_pool[g * 256 + j] = 0.f;     // restore for next run
    }
    __syncthreads();
    if (t == 0) g_cnt[g] = 0;          // restore (after c read)
    float acc = fc1b[t];
    for (int k = 0; k < 256; k++) acc += sp[k] * fc1w[k * 128 + t];
    sg[t] = selu_f(acc);
    __syncthreads();
    if (t < 2) {
        float a = fc2b[t];
        for (int k = 0; k < 128; k++) a += sg[k] * fc2w[k * 2 + t];
        slog[t] = a;
    }
    __syncthreads();
    if (t < 2) {
        float m = fmaxf(slog[0], slog[1]);
        float lse = m + logf(expf(slog[0] - m) + expf(slog[1] - m));
        out[g * 2 + t] = slog[t] - lse;
    }
}

// ---------------- launch -----------------------------------------------------
extern "C" void kernel_launch(void* const* d_in, const int* in_sizes, int n_in,
                              void* d_out, int out_size) {
    const float* x     = (const float*)d_in[0];
    const void*  ei    = d_in[1];
    const void*  batch = d_in[2];
    const float* W1  = (const float*)d_in[3];
    const float* b1  = (const float*)d_in[4];
    const float* W2  = (const float*)d_in[5];
    const float* b2  = (const float*)d_in[6];
    const float* f1w = (const float*)d_in[7];
    const float* f1b = (const float*)d_in[8];
    const float* f2w = (const float*)d_in[9];
    const float* f2b = (const float*)d_in[10];
    float* out = (float*)d_out;

    deg_count_kernel<<<(N_EDGES + 255) / 256, 256>>>(ei, batch);
    scan_one<<<N_SCANBLK, SCAN_B>>>();
    fill_kernel<<<(N_EDGES + 255) / 256, 256>>>(ei);

    gemm1_fused<<<(N_NODES + 31) / 32, 256>>>(x, W1, b1);
    agg2_kernel<<<(N_NODES * 32 + 255) / 256, 256>>>();
    {
        dim3 grid((N_NODES + GM - 1) / GM, 256 / GN);
        gemm2_tc<<<grid, 256>>>(W2, b2, batch);
    }
    head_kernel<<<N_GRAPHS, 128>>>(f1w, f1b, f2w, f2b, out);
}